// round 1
// baseline (speedup 1.0000x reference)
#include <cuda_runtime.h>
#include <math.h>

#define BB  8
#define TT  2048
#define CH  1024
#define NEGINF (-4294967295.0f)

// ---------------- scratch (no allocations allowed) ----------------
__device__ float g_f1[BB * TT * CH];                 // 64 MB
__device__ float g_f2[BB * TT * CH];                 // 64 MB
__device__ float g_S [(size_t)BB * TT * TT];         // 128 MB

enum { EPI_NONE = 0, EPI_RELU, EPI_RELU_DIAG, EPI_SCORE, EPI_ADD, EPI_BIAS_RELU, EPI_BIAS };

// ---------------- generic tiled fp32 GEMM: C = A(MxK) * B ----------------
// TRANSB=false: B is [K,N] row-major (ldb=N). TRANSB=true: B is [N,K] row-major (ldb=K).
// A is always row-major with lda=K. All of M,N,K are multiples of 128 here.
template <int EPI, bool TRANSB>
__global__ __launch_bounds__(256, 2)
void gemm_k(const float* __restrict__ A, const float* __restrict__ Bm, float* __restrict__ Cm,
            int M, int N, int K,
            long sA, long sB, long sC,
            const float* __restrict__ vec, long sVec,     // diag / bias / key_mask
            const float* __restrict__ addsrc, long sAdd,  // residual
            float scale)
{
    __shared__ float As[8][128];
    __shared__ float Bs[8][128];

    const int z = blockIdx.z;
    A  += (long)z * sA;
    Bm += (long)z * sB;
    Cm += (long)z * sC;
    const float* vv = vec    ? vec    + (long)z * sVec : nullptr;
    const float* ad = addsrc ? addsrc + (long)z * sAdd : nullptr;

    const int tid = threadIdx.x;
    const int rowBase = blockIdx.y * 128;
    const int colBase = blockIdx.x * 128;
    const int tm = tid >> 4, tn = tid & 15;
    const int lr = tid >> 1;            // 0..127
    const int lk = (tid & 1) * 4;       // 0 or 4

    float acc[8][8];
#pragma unroll
    for (int i = 0; i < 8; i++)
#pragma unroll
        for (int j = 0; j < 8; j++) acc[i][j] = 0.f;

    const float* Aptr = A + (long)(rowBase + lr) * K + lk;

    for (int k0 = 0; k0 < K; k0 += 8) {
        float4 av = *(const float4*)(Aptr + k0);
        As[lk + 0][lr] = av.x; As[lk + 1][lr] = av.y;
        As[lk + 2][lr] = av.z; As[lk + 3][lr] = av.w;
        if (TRANSB) {
            float4 bv = *(const float4*)(Bm + (long)(colBase + lr) * K + k0 + lk);
            Bs[lk + 0][lr] = bv.x; Bs[lk + 1][lr] = bv.y;
            Bs[lk + 2][lr] = bv.z; Bs[lk + 3][lr] = bv.w;
        } else {
            int kr = tid >> 5, cc = (tid & 31) * 4;
            *(float4*)&Bs[kr][cc] = *(const float4*)(Bm + (long)(k0 + kr) * N + colBase + cc);
        }
        __syncthreads();
#pragma unroll
        for (int kk = 0; kk < 8; kk++) {
            float4 a0 = *(const float4*)&As[kk][tm * 4];
            float4 a1 = *(const float4*)&As[kk][64 + tm * 4];
            float4 b0 = *(const float4*)&Bs[kk][tn * 4];
            float4 b1 = *(const float4*)&Bs[kk][64 + tn * 4];
            float a[8]  = {a0.x, a0.y, a0.z, a0.w, a1.x, a1.y, a1.z, a1.w};
            float bb[8] = {b0.x, b0.y, b0.z, b0.w, b1.x, b1.y, b1.z, b1.w};
#pragma unroll
            for (int i = 0; i < 8; i++)
#pragma unroll
                for (int j = 0; j < 8; j++) acc[i][j] += a[i] * bb[j];
        }
        __syncthreads();
    }

    // epilogue
#pragma unroll
    for (int i = 0; i < 8; i++) {
        int r = rowBase + (i < 4 ? tm * 4 + i : 64 + tm * 4 + i - 4);
#pragma unroll
        for (int j = 0; j < 8; j++) {
            int c = colBase + (j < 4 ? tn * 4 + j : 64 + tn * 4 + j - 4);
            float v = acc[i][j];
            if (EPI == EPI_RELU)      v = v > 0.f ? v : 0.f;
            if (EPI == EPI_RELU_DIAG) v = (v > 0.f ? v : 0.f) * vv[c];
            if (EPI == EPI_SCORE)     { v *= scale; if (vv[c] == 0.f) v = NEGINF; }
            if (EPI == EPI_ADD)       v += ad[(long)r * N + c];
            if (EPI == EPI_BIAS_RELU) { v += vv[c]; v = v > 0.f ? v : 0.f; }
            if (EPI == EPI_BIAS)      v += vv[c];
            Cm[(long)r * N + c] = v;
        }
    }
}

// ---------------- softmax over rows of length TT, times query mask ----------------
__global__ __launch_bounds__(256)
void softmax_k(float* __restrict__ S, const float* __restrict__ qmask)
{
    __shared__ float sh[8];
    const long row = blockIdx.x;
    float* p = S + row * TT;
    const int tid = threadIdx.x, lane = tid & 31, w = tid >> 5;

    float x[8];
#pragma unroll
    for (int i = 0; i < 8; i++) x[i] = p[tid + i * 256];

    float m = -3.4e38f;
#pragma unroll
    for (int i = 0; i < 8; i++) m = fmaxf(m, x[i]);
#pragma unroll
    for (int o = 16; o; o >>= 1) m = fmaxf(m, __shfl_xor_sync(0xffffffffu, m, o));
    if (lane == 0) sh[w] = m;
    __syncthreads();
#pragma unroll
    for (int i = 0; i < 8; i++) m = fmaxf(m, sh[i]);

    float s = 0.f;
#pragma unroll
    for (int i = 0; i < 8; i++) { x[i] = expf(x[i] - m); s += x[i]; }
#pragma unroll
    for (int o = 16; o; o >>= 1) s += __shfl_xor_sync(0xffffffffu, s, o);
    __syncthreads();
    if (lane == 0) sh[w] = s;
    __syncthreads();
    s = 0.f;
#pragma unroll
    for (int i = 0; i < 8; i++) s += sh[i];

    const float inv = qmask[row] / s;
#pragma unroll
    for (int i = 0; i < 8; i++) p[tid + i * 256] = x[i] * inv;
}

// ---------------- LayerNorm over rows of length CH ----------------
__global__ __launch_bounds__(256)
void ln_k(const float* __restrict__ in, float* __restrict__ out,
          const float* __restrict__ gamma, const float* __restrict__ beta)
{
    __shared__ float sh[8];
    const long row = blockIdx.x;
    const float* p = in + row * CH;
    const int tid = threadIdx.x, lane = tid & 31, w = tid >> 5;
    const int c = tid * 4;

    float4 xv = *(const float4*)(p + c);
    float s = xv.x + xv.y + xv.z + xv.w;
#pragma unroll
    for (int o = 16; o; o >>= 1) s += __shfl_xor_sync(0xffffffffu, s, o);
    if (lane == 0) sh[w] = s;
    __syncthreads();
    float tot = 0.f;
#pragma unroll
    for (int i = 0; i < 8; i++) tot += sh[i];
    const float mu = tot * (1.f / CH);

    float d0 = xv.x - mu, d1 = xv.y - mu, d2 = xv.z - mu, d3 = xv.w - mu;
    float q = d0 * d0 + d1 * d1 + d2 * d2 + d3 * d3;
#pragma unroll
    for (int o = 16; o; o >>= 1) q += __shfl_xor_sync(0xffffffffu, q, o);
    __syncthreads();
    if (lane == 0) sh[w] = q;
    __syncthreads();
    float vtot = 0.f;
#pragma unroll
    for (int i = 0; i < 8; i++) vtot += sh[i];
    const float rstd = rsqrtf(vtot * (1.f / CH) + 1e-6f);

    float4 g  = *(const float4*)(gamma + c);
    float4 be = *(const float4*)(beta + c);
    float4 o4;
    o4.x = d0 * rstd * g.x + be.x;
    o4.y = d1 * rstd * g.y + be.y;
    o4.z = d2 * rstd * g.z + be.z;
    o4.w = d3 * rstd * g.w + be.w;
    *(float4*)(out + row * CH + c) = o4;
}

// ---------------- launch ----------------
extern "C" void kernel_launch(void* const* d_in, const int* in_sizes, int n_in,
                              void* d_out, int out_size)
{
    const float* Q     = (const float*)d_in[0];
    const float* Kk    = (const float*)d_in[1];
    const float* kmask = (const float*)d_in[2];
    const float* qmask = (const float*)d_in[3];
    const float* u     = (const float*)d_in[4];
    const float* dd    = (const float*)d_in[5];
    const float* W1    = (const float*)d_in[6];
    const float* b1    = (const float*)d_in[7];
    const float* W2    = (const float*)d_in[8];
    const float* b2    = (const float*)d_in[9];
    const float* gamma = (const float*)d_in[10];
    const float* beta  = (const float*)d_in[11];

    float *f1, *f2, *S;
    cudaGetSymbolAddress((void**)&f1, g_f1);
    cudaGetSymbolAddress((void**)&f2, g_f2);
    cudaGetSymbolAddress((void**)&S,  g_S);

    const long NTC = (long)BB * TT * CH;
    float* out2 = (float*)d_out;
    if ((long)out_size >= 2 * NTC) {
        // output tuple = (queries, out2) concatenated
        cudaMemcpyAsync(d_out, Q, NTC * sizeof(float), cudaMemcpyDeviceToDevice);
        out2 = (float*)d_out + NTC;
    }

    const dim3 blk(256);
    const long TC = (long)TT * CH;
    const long TTl = (long)TT * TT;

    // 1) f1 = relu(Q @ u) * d_diag      [16384 x 1024]
    gemm_k<EPI_RELU_DIAG, false><<<dim3(CH / 128, BB * TT / 128, 1), blk>>>(
        Q, u, f1, BB * TT, CH, CH, 0, 0, 0, dd, 0, nullptr, 0, 0.f);

    // 2) f2 = relu(K @ u)
    gemm_k<EPI_RELU, false><<<dim3(CH / 128, BB * TT / 128, 1), blk>>>(
        Kk, u, f2, BB * TT, CH, CH, 0, 0, 0, nullptr, 0, nullptr, 0, 0.f);

    // 3) S[b] = (f1[b] @ f2[b]^T) / 32, key-masked   [8 x 2048 x 2048]
    gemm_k<EPI_SCORE, true><<<dim3(TT / 128, TT / 128, BB), blk>>>(
        f1, f2, S, TT, TT, CH, TC, TC, TTl, kmask, TT, nullptr, 0, 1.0f / 32.0f);

    // 4) softmax rows, * query_mask
    softmax_k<<<BB * TT, 256>>>(S, qmask);

    // 5) ctx = attn @ K + Q  -> f1
    gemm_k<EPI_ADD, false><<<dim3(CH / 128, TT / 128, BB), blk>>>(
        S, Kk, f1, TT, CH, TT, TTl, TC, TC, nullptr, 0, Q, TC, 0.f);

    // 6) LayerNorm -> f2
    ln_k<<<BB * TT, 256>>>(f1, f2, gamma, beta);

    // 7) h = relu(f2 @ W1 + b1) -> S (reused as [16384 x 1024] scratch)
    gemm_k<EPI_BIAS_RELU, false><<<dim3(CH / 128, BB * TT / 128, 1), blk>>>(
        f2, W1, S, BB * TT, CH, CH, 0, 0, 0, b1, 0, nullptr, 0, 0.f);

    // 8) out2 = h @ W2 + b2
    gemm_k<EPI_BIAS, false><<<dim3(CH / 128, BB * TT / 128, 1), blk>>>(
        S, W2, out2, BB * TT, CH, CH, 0, 0, 0, b2, 0, nullptr, 0, 0.f);
}

// round 2
// speedup vs baseline: 2.5867x; 2.5867x over previous
#include <cuda_runtime.h>
#include <math.h>
#include <stdint.h>

#define BB  8
#define TT  2048
#define CH  1024
#define NEGINF (-4294967295.0f)

// ---------------- scratch (no allocations allowed) ----------------
__device__ float g_f1[BB * TT * CH];                 // 64 MB
__device__ float g_f2[BB * TT * CH];                 // 64 MB
__device__ float g_S [(size_t)BB * TT * TT];         // 128 MB

enum { EPI_NONE = 0, EPI_RELU, EPI_RELU_DIAG, EPI_SCORE, EPI_ADD, EPI_BIAS_RELU, EPI_BIAS };

__device__ __forceinline__ uint32_t f2tf(float f) {
    uint32_t u;
    asm("cvt.rna.tf32.f32 %0, %1;" : "=r"(u) : "f"(f));
    return u;
}

__device__ __forceinline__ void mma_tf32(float* d, const uint32_t* a, const uint32_t* b) {
    asm volatile(
        "mma.sync.aligned.m16n8k8.row.col.f32.tf32.tf32.f32 "
        "{%0,%1,%2,%3}, {%4,%5,%6,%7}, {%8,%9}, {%0,%1,%2,%3};"
        : "+f"(d[0]), "+f"(d[1]), "+f"(d[2]), "+f"(d[3])
        : "r"(a[0]), "r"(a[1]), "r"(a[2]), "r"(a[3]), "r"(b[0]), "r"(b[1]));
}

// ---------------- TF32 tensor-core GEMM: C = A(MxK) * B ----------------
// A row-major (lda=K). TRANSB=false: B [K,N] (ldb=N). TRANSB=true: B [N,K] (ldb=K).
// CTA tile 128x128, K-tile 16, 8 warps (2m x 4n) of 64x32, m16n8k8 tf32 mma.
template <int EPI, bool TRANSB>
__global__ __launch_bounds__(256)
void gemm_tc(const float* __restrict__ A, const float* __restrict__ Bm, float* __restrict__ Cm,
             int M, int N, int K,
             long sA, long sB, long sC,
             const float* __restrict__ vec, long sVec,     // diag / bias / key_mask
             const float* __restrict__ addsrc, long sAdd,  // residual
             float scale)
{
    __shared__ uint32_t As[2][128][20];   // [m][k], pad 20 -> conflict-free frag loads
    __shared__ uint32_t Bs[2][16][136];   // [k][n], pad 136 -> conflict-free frag loads

    const int z = blockIdx.z;
    A  += (long)z * sA;
    Bm += (long)z * sB;
    Cm += (long)z * sC;
    const float* vv = vec    ? vec    + (long)z * sVec : nullptr;
    const float* ad = addsrc ? addsrc + (long)z * sAdd : nullptr;

    const int tid  = threadIdx.x;
    const int lane = tid & 31;
    const int warp = tid >> 5;
    const int wm = warp >> 2;        // 0..1
    const int wn = warp & 3;         // 0..3
    const int rowBase = blockIdx.y * 128;
    const int colBase = blockIdx.x * 128;
    const int lda = K;
    const int ldb = TRANSB ? K : N;

    // staging indices
    const int ar = tid >> 2, ac = (tid & 3) * 4;     // A: rows ar, ar+64; k-cols ac..ac+3
    const int bk = tid >> 5, bc = (tid & 31) * 4;    // B non-trans: k rows bk, bk+8
    const int bn = tid >> 2, bkc = (tid & 3) * 4;    // B trans: n rows bn, bn+64

    float acc[4][4][4];
#pragma unroll
    for (int mi = 0; mi < 4; mi++)
#pragma unroll
        for (int ni = 0; ni < 4; ni++)
#pragma unroll
            for (int e = 0; e < 4; e++) acc[mi][ni][e] = 0.f;

    const float* aptr0 = A + (long)(rowBase + ar) * lda + ac;
    const float* aptr1 = aptr0 + (long)64 * lda;

    float4 av0, av1, bv0, bv1;

#define LD_TILE(k0)                                                                      \
    do {                                                                                 \
        av0 = *(const float4*)(aptr0 + (k0));                                            \
        av1 = *(const float4*)(aptr1 + (k0));                                            \
        if (TRANSB) {                                                                    \
            bv0 = *(const float4*)(Bm + (long)(colBase + bn) * ldb + (k0) + bkc);        \
            bv1 = *(const float4*)(Bm + (long)(colBase + bn + 64) * ldb + (k0) + bkc);   \
        } else {                                                                         \
            bv0 = *(const float4*)(Bm + (long)((k0) + bk) * ldb + colBase + bc);         \
            bv1 = *(const float4*)(Bm + (long)((k0) + bk + 8) * ldb + colBase + bc);     \
        }                                                                                \
    } while (0)

#define ST_TILE(buf)                                                                     \
    do {                                                                                 \
        As[buf][ar][ac + 0] = f2tf(av0.x); As[buf][ar][ac + 1] = f2tf(av0.y);            \
        As[buf][ar][ac + 2] = f2tf(av0.z); As[buf][ar][ac + 3] = f2tf(av0.w);            \
        As[buf][ar + 64][ac + 0] = f2tf(av1.x); As[buf][ar + 64][ac + 1] = f2tf(av1.y);  \
        As[buf][ar + 64][ac + 2] = f2tf(av1.z); As[buf][ar + 64][ac + 3] = f2tf(av1.w);  \
        if (TRANSB) {                                                                    \
            Bs[buf][bkc + 0][bn] = f2tf(bv0.x); Bs[buf][bkc + 1][bn] = f2tf(bv0.y);      \
            Bs[buf][bkc + 2][bn] = f2tf(bv0.z); Bs[buf][bkc + 3][bn] = f2tf(bv0.w);      \
            Bs[buf][bkc + 0][bn + 64] = f2tf(bv1.x);                                     \
            Bs[buf][bkc + 1][bn + 64] = f2tf(bv1.y);                                     \
            Bs[buf][bkc + 2][bn + 64] = f2tf(bv1.z);                                     \
            Bs[buf][bkc + 3][bn + 64] = f2tf(bv1.w);                                     \
        } else {                                                                         \
            Bs[buf][bk][bc + 0] = f2tf(bv0.x); Bs[buf][bk][bc + 1] = f2tf(bv0.y);        \
            Bs[buf][bk][bc + 2] = f2tf(bv0.z); Bs[buf][bk][bc + 3] = f2tf(bv0.w);        \
            Bs[buf][bk + 8][bc + 0] = f2tf(bv1.x); Bs[buf][bk + 8][bc + 1] = f2tf(bv1.y);\
            Bs[buf][bk + 8][bc + 2] = f2tf(bv1.z); Bs[buf][bk + 8][bc + 3] = f2tf(bv1.w);\
        }                                                                                \
    } while (0)

    LD_TILE(0);
    ST_TILE(0);
    __syncthreads();

    const int nIter = K / 16;
    for (int it = 0; it < nIter; ++it) {
        const int buf = it & 1;
        if (it + 1 < nIter) LD_TILE((it + 1) * 16);

#pragma unroll
        for (int ks = 0; ks < 16; ks += 8) {
            uint32_t af[4][4], bf[4][2];
#pragma unroll
            for (int mi = 0; mi < 4; mi++) {
                int r = wm * 64 + mi * 16 + (lane >> 2);
                int c = ks + (lane & 3);
                af[mi][0] = As[buf][r][c];
                af[mi][1] = As[buf][r + 8][c];
                af[mi][2] = As[buf][r][c + 4];
                af[mi][3] = As[buf][r + 8][c + 4];
            }
#pragma unroll
            for (int ni = 0; ni < 4; ni++) {
                int n = wn * 32 + ni * 8 + (lane >> 2);
                bf[ni][0] = Bs[buf][ks + (lane & 3)][n];
                bf[ni][1] = Bs[buf][ks + 4 + (lane & 3)][n];
            }
#pragma unroll
            for (int mi = 0; mi < 4; mi++)
#pragma unroll
                for (int ni = 0; ni < 4; ni++)
                    mma_tf32(acc[mi][ni], af[mi], bf[ni]);
        }

        if (it + 1 < nIter) ST_TILE((it + 1) & 1);
        __syncthreads();
    }

    // ---------------- epilogue ----------------
#pragma unroll
    for (int mi = 0; mi < 4; mi++) {
        const int rBase = rowBase + wm * 64 + mi * 16 + (lane >> 2);
#pragma unroll
        for (int ni = 0; ni < 4; ni++) {
            const int c = colBase + wn * 32 + ni * 8 + (lane & 3) * 2;
#pragma unroll
            for (int p = 0; p < 2; p++) {
                const int r = rBase + p * 8;
                float v0 = acc[mi][ni][p * 2 + 0];
                float v1 = acc[mi][ni][p * 2 + 1];
                if (EPI == EPI_RELU)      { v0 = fmaxf(v0, 0.f); v1 = fmaxf(v1, 0.f); }
                if (EPI == EPI_RELU_DIAG) { v0 = fmaxf(v0, 0.f) * vv[c]; v1 = fmaxf(v1, 0.f) * vv[c + 1]; }
                if (EPI == EPI_SCORE)     { v0 *= scale; v1 *= scale;
                                            if (vv[c] == 0.f)     v0 = NEGINF;
                                            if (vv[c + 1] == 0.f) v1 = NEGINF; }
                if (EPI == EPI_ADD)       { float2 a2 = *(const float2*)(ad + (long)r * N + c);
                                            v0 += a2.x; v1 += a2.y; }
                if (EPI == EPI_BIAS_RELU) { v0 = fmaxf(v0 + vv[c], 0.f); v1 = fmaxf(v1 + vv[c + 1], 0.f); }
                if (EPI == EPI_BIAS)      { v0 += vv[c]; v1 += vv[c + 1]; }
                float2 o2 = make_float2(v0, v1);
                *(float2*)(Cm + (long)r * N + c) = o2;
            }
        }
    }
#undef LD_TILE
#undef ST_TILE
}

// ---------------- softmax over rows of length TT, times query mask ----------------
__global__ __launch_bounds__(256)
void softmax_k(float* __restrict__ S, const float* __restrict__ qmask)
{
    __shared__ float sh[8];
    const long row = blockIdx.x;
    float* p = S + row * TT;
    const int tid = threadIdx.x, lane = tid & 31, w = tid >> 5;

    float x[8];
#pragma unroll
    for (int i = 0; i < 8; i++) x[i] = p[tid + i * 256];

    float m = -3.4e38f;
#pragma unroll
    for (int i = 0; i < 8; i++) m = fmaxf(m, x[i]);
#pragma unroll
    for (int o = 16; o; o >>= 1) m = fmaxf(m, __shfl_xor_sync(0xffffffffu, m, o));
    if (lane == 0) sh[w] = m;
    __syncthreads();
#pragma unroll
    for (int i = 0; i < 8; i++) m = fmaxf(m, sh[i]);

    float s = 0.f;
#pragma unroll
    for (int i = 0; i < 8; i++) { x[i] = expf(x[i] - m); s += x[i]; }
#pragma unroll
    for (int o = 16; o; o >>= 1) s += __shfl_xor_sync(0xffffffffu, s, o);
    __syncthreads();
    if (lane == 0) sh[w] = s;
    __syncthreads();
    s = 0.f;
#pragma unroll
    for (int i = 0; i < 8; i++) s += sh[i];

    const float inv = qmask[row] / s;
#pragma unroll
    for (int i = 0; i < 8; i++) p[tid + i * 256] = x[i] * inv;
}

// ---------------- LayerNorm over rows of length CH ----------------
__global__ __launch_bounds__(256)
void ln_k(const float* __restrict__ in, float* __restrict__ out,
          const float* __restrict__ gamma, const float* __restrict__ beta)
{
    __shared__ float sh[8];
    const long row = blockIdx.x;
    const float* p = in + row * CH;
    const int tid = threadIdx.x, lane = tid & 31, w = tid >> 5;
    const int c = tid * 4;

    float4 xv = *(const float4*)(p + c);
    float s = xv.x + xv.y + xv.z + xv.w;
#pragma unroll
    for (int o = 16; o; o >>= 1) s += __shfl_xor_sync(0xffffffffu, s, o);
    if (lane == 0) sh[w] = s;
    __syncthreads();
    float tot = 0.f;
#pragma unroll
    for (int i = 0; i < 8; i++) tot += sh[i];
    const float mu = tot * (1.f / CH);

    float d0 = xv.x - mu, d1 = xv.y - mu, d2 = xv.z - mu, d3 = xv.w - mu;
    float q = d0 * d0 + d1 * d1 + d2 * d2 + d3 * d3;
#pragma unroll
    for (int o = 16; o; o >>= 1) q += __shfl_xor_sync(0xffffffffu, q, o);
    __syncthreads();
    if (lane == 0) sh[w] = q;
    __syncthreads();
    float vtot = 0.f;
#pragma unroll
    for (int i = 0; i < 8; i++) vtot += sh[i];
    const float rstd = rsqrtf(vtot * (1.f / CH) + 1e-6f);

    float4 g  = *(const float4*)(gamma + c);
    float4 be = *(const float4*)(beta + c);
    float4 o4;
    o4.x = d0 * rstd * g.x + be.x;
    o4.y = d1 * rstd * g.y + be.y;
    o4.z = d2 * rstd * g.z + be.z;
    o4.w = d3 * rstd * g.w + be.w;
    *(float4*)(out + row * CH + c) = o4;
}

// ---------------- launch ----------------
extern "C" void kernel_launch(void* const* d_in, const int* in_sizes, int n_in,
                              void* d_out, int out_size)
{
    const float* Q     = (const float*)d_in[0];
    const float* Kk    = (const float*)d_in[1];
    const float* kmask = (const float*)d_in[2];
    const float* qmask = (const float*)d_in[3];
    const float* u     = (const float*)d_in[4];
    const float* dd    = (const float*)d_in[5];
    const float* W1    = (const float*)d_in[6];
    const float* b1    = (const float*)d_in[7];
    const float* W2    = (const float*)d_in[8];
    const float* b2    = (const float*)d_in[9];
    const float* gamma = (const float*)d_in[10];
    const float* beta  = (const float*)d_in[11];

    float *f1, *f2, *S;
    cudaGetSymbolAddress((void**)&f1, g_f1);
    cudaGetSymbolAddress((void**)&f2, g_f2);
    cudaGetSymbolAddress((void**)&S,  g_S);

    const long NTC = (long)BB * TT * CH;
    float* out2 = (float*)d_out;
    if ((long)out_size >= 2 * NTC) {
        cudaMemcpyAsync(d_out, Q, NTC * sizeof(float), cudaMemcpyDeviceToDevice);
        out2 = (float*)d_out + NTC;
    }

    const dim3 blk(256);
    const long TC = (long)TT * CH;
    const long TTl = (long)TT * TT;

    // 1) f1 = relu(Q @ u) * d_diag      [16384 x 1024]
    gemm_tc<EPI_RELU_DIAG, false><<<dim3(CH / 128, BB * TT / 128, 1), blk>>>(
        Q, u, f1, BB * TT, CH, CH, 0, 0, 0, dd, 0, nullptr, 0, 0.f);

    // 2) f2 = relu(K @ u)
    gemm_tc<EPI_RELU, false><<<dim3(CH / 128, BB * TT / 128, 1), blk>>>(
        Kk, u, f2, BB * TT, CH, CH, 0, 0, 0, nullptr, 0, nullptr, 0, 0.f);

    // 3) S[b] = (f1[b] @ f2[b]^T) / 32, key-masked   [8 x 2048 x 2048]
    gemm_tc<EPI_SCORE, true><<<dim3(TT / 128, TT / 128, BB), blk>>>(
        f1, f2, S, TT, TT, CH, TC, TC, TTl, kmask, TT, nullptr, 0, 1.0f / 32.0f);

    // 4) softmax rows, * query_mask
    softmax_k<<<BB * TT, 256>>>(S, qmask);

    // 5) ctx = attn @ K + Q  -> f1
    gemm_tc<EPI_ADD, false><<<dim3(CH / 128, TT / 128, BB), blk>>>(
        S, Kk, f1, TT, CH, TT, TTl, TC, TC, nullptr, 0, Q, TC, 0.f);

    // 6) LayerNorm -> f2
    ln_k<<<BB * TT, 256>>>(f1, f2, gamma, beta);

    // 7) h = relu(f2 @ W1 + b1) -> S (reused as [16384 x 1024] scratch)
    gemm_tc<EPI_BIAS_RELU, false><<<dim3(CH / 128, BB * TT / 128, 1), blk>>>(
        f2, W1, S, BB * TT, CH, CH, 0, 0, 0, b1, 0, nullptr, 0, 0.f);

    // 8) out2 = h @ W2 + b2
    gemm_tc<EPI_BIAS, false><<<dim3(CH / 128, BB * TT / 128, 1), blk>>>(
        S, W2, out2, BB * TT, CH, CH, 0, 0, 0, b2, 0, nullptr, 0, 0.f);
}

// round 3
// speedup vs baseline: 3.2343x; 1.2503x over previous
#include <cuda_runtime.h>
#include <cuda_fp16.h>
#include <math.h>
#include <stdint.h>

#define BB  8
#define TT  2048
#define CH  1024
#define NEGINF (-4294967295.0f)

// ---------------- scratch (no allocations allowed) ----------------
__device__ float g_f1[BB * TT * CH];                 // 64 MB
__device__ float g_f2[BB * TT * CH];                 // 64 MB
__device__ float g_S [(size_t)BB * TT * TT];         // 128 MB

enum { EPI_NONE = 0, EPI_RELU, EPI_RELU_DIAG, EPI_SCORE, EPI_ADD, EPI_BIAS_RELU, EPI_BIAS };

__device__ __forceinline__ uint32_t packh2(float lo, float hi) {
    __half2 h = __floats2half2_rn(lo, hi);   // lo -> low 16 bits
    return *(uint32_t*)&h;
}

__device__ __forceinline__ void mma_f16(float* d, const uint32_t* a, const uint32_t* b) {
    asm volatile(
        "mma.sync.aligned.m16n8k16.row.col.f32.f16.f16.f32 "
        "{%0,%1,%2,%3}, {%4,%5,%6,%7}, {%8,%9}, {%0,%1,%2,%3};"
        : "+f"(d[0]), "+f"(d[1]), "+f"(d[2]), "+f"(d[3])
        : "r"(a[0]), "r"(a[1]), "r"(a[2]), "r"(a[3]), "r"(b[0]), "r"(b[1]));
}

// ---------------- FP16 tensor-core GEMM: C = A(MxK) * B ----------------
// A row-major (lda=K). TRANSB=false: B [K,N] (ldb=N). TRANSB=true: B [N,K] (ldb=K).
// CTA tile 128x128, K-tile 16, 8 warps (2m x 4n) of 64x32, m16n8k16 f16 mma, fp32 acc.
// Smem layouts (packed half2 words):
//   As32[m][kw]  kw=k/2 (0..7), row stride 12 words  -> frag loads conflict-free
//   Bs32[kw][n]  word = pack(B[2kw][n], B[2kw+1][n]), row stride 136 -> conflict-free
template <int EPI, bool TRANSB>
__global__ __launch_bounds__(256)
void gemm_tc(const float* __restrict__ A, const float* __restrict__ Bm, float* __restrict__ Cm,
             int M, int N, int K,
             long sA, long sB, long sC,
             const float* __restrict__ vec, long sVec,     // diag / bias / key_mask
             const float* __restrict__ addsrc, long sAdd,  // residual
             float scale)
{
    __shared__ uint32_t As32[2][128][12];
    __shared__ uint32_t Bs32[2][8][136];

    const int z = blockIdx.z;
    A  += (long)z * sA;
    Bm += (long)z * sB;
    Cm += (long)z * sC;
    const float* vv = vec    ? vec    + (long)z * sVec : nullptr;
    const float* ad = addsrc ? addsrc + (long)z * sAdd : nullptr;

    const int tid  = threadIdx.x;
    const int lane = tid & 31;
    const int warp = tid >> 5;
    const int wm = warp >> 2;        // 0..1
    const int wn = warp & 3;         // 0..3
    const int gr = lane >> 2;        // 0..7
    const int gj = lane & 3;         // 0..3
    const int rowBase = blockIdx.y * 128;
    const int colBase = blockIdx.x * 128;
    const int lda = K;
    const int ldb = TRANSB ? K : N;

    // ---- staging index precompute ----
    // A: thread handles row (tid>>1), k-chunk (tid&1)*8 .. +7
    const int am  = tid >> 1;
    const int akc = (tid & 1) * 8;
    const float* aptr = A + (long)(rowBase + am) * lda + akc;
    // B non-trans: thread handles k-pair (tid>>5), n quad (tid&31)*4
    const int bkp = tid >> 5;
    const int bn4 = (tid & 31) * 4;
    const float* bptrB = Bm + (long)(2 * bkp) * ldb + colBase + bn4;
    // B trans: thread handles n row (tid>>1), k-chunk (tid&1)*8
    const int btn  = tid >> 1;
    const int btkc = (tid & 1) * 8;
    const float* bptrT = Bm + (long)(colBase + btn) * ldb + btkc;

    float acc[4][4][4];
#pragma unroll
    for (int mi = 0; mi < 4; mi++)
#pragma unroll
        for (int ni = 0; ni < 4; ni++)
#pragma unroll
            for (int e = 0; e < 4; e++) acc[mi][ni][e] = 0.f;

    float4 av0, av1, bv0, bv1;

#define LD_TILE(k0)                                                           \
    do {                                                                      \
        av0 = *(const float4*)(aptr + (k0));                                  \
        av1 = *(const float4*)(aptr + (k0) + 4);                              \
        if (TRANSB) {                                                         \
            bv0 = *(const float4*)(bptrT + (k0));                             \
            bv1 = *(const float4*)(bptrT + (k0) + 4);                         \
        } else {                                                              \
            bv0 = *(const float4*)(bptrB + (long)(k0) * ldb);                 \
            bv1 = *(const float4*)(bptrB + (long)(k0) * ldb + ldb);           \
        }                                                                     \
    } while (0)

#define ST_TILE(buf)                                                          \
    do {                                                                      \
        uint4 aw;                                                             \
        aw.x = packh2(av0.x, av0.y); aw.y = packh2(av0.z, av0.w);             \
        aw.z = packh2(av1.x, av1.y); aw.w = packh2(av1.z, av1.w);             \
        *(uint4*)&As32[buf][am][(tid & 1) * 4] = aw;                          \
        if (TRANSB) {                                                         \
            const int kw = (tid & 1) * 4;                                     \
            Bs32[buf][kw + 0][btn] = packh2(bv0.x, bv0.y);                    \
            Bs32[buf][kw + 1][btn] = packh2(bv0.z, bv0.w);                    \
            Bs32[buf][kw + 2][btn] = packh2(bv1.x, bv1.y);                    \
            Bs32[buf][kw + 3][btn] = packh2(bv1.z, bv1.w);                    \
        } else {                                                              \
            uint4 bw;                                                         \
            bw.x = packh2(bv0.x, bv1.x); bw.y = packh2(bv0.y, bv1.y);         \
            bw.z = packh2(bv0.z, bv1.z); bw.w = packh2(bv0.w, bv1.w);         \
            *(uint4*)&Bs32[buf][bkp][bn4] = bw;                               \
        }                                                                     \
    } while (0)

    LD_TILE(0);
    ST_TILE(0);
    __syncthreads();

    const int nIter = K / 16;
    for (int it = 0; it < nIter; ++it) {
        const int buf = it & 1;
        if (it + 1 < nIter) LD_TILE((it + 1) * 16);

        // fragment loads (one k16 pass covers the whole tile)
        uint32_t af[4][4], bf[4][2];
#pragma unroll
        for (int mi = 0; mi < 4; mi++) {
            const int r = wm * 64 + mi * 16 + gr;
            af[mi][0] = As32[buf][r][gj];
            af[mi][1] = As32[buf][r + 8][gj];
            af[mi][2] = As32[buf][r][gj + 4];
            af[mi][3] = As32[buf][r + 8][gj + 4];
        }
#pragma unroll
        for (int ni = 0; ni < 4; ni++) {
            const int n = wn * 32 + ni * 8 + gr;
            bf[ni][0] = Bs32[buf][gj][n];
            bf[ni][1] = Bs32[buf][gj + 4][n];
        }
#pragma unroll
        for (int mi = 0; mi < 4; mi++)
#pragma unroll
            for (int ni = 0; ni < 4; ni++)
                mma_f16(acc[mi][ni], af[mi], bf[ni]);

        if (it + 1 < nIter) ST_TILE((it + 1) & 1);
        __syncthreads();
    }

    // ---------------- epilogue ----------------
#pragma unroll
    for (int mi = 0; mi < 4; mi++) {
        const int rBase = rowBase + wm * 64 + mi * 16 + gr;
#pragma unroll
        for (int ni = 0; ni < 4; ni++) {
            const int c = colBase + wn * 32 + ni * 8 + gj * 2;
#pragma unroll
            for (int p = 0; p < 2; p++) {
                const int r = rBase + p * 8;
                float v0 = acc[mi][ni][p * 2 + 0];
                float v1 = acc[mi][ni][p * 2 + 1];
                if (EPI == EPI_RELU)      { v0 = fmaxf(v0, 0.f); v1 = fmaxf(v1, 0.f); }
                if (EPI == EPI_RELU_DIAG) { v0 = fmaxf(v0, 0.f) * vv[c]; v1 = fmaxf(v1, 0.f) * vv[c + 1]; }
                if (EPI == EPI_SCORE)     { v0 *= scale; v1 *= scale;
                                            if (vv[c] == 0.f)     v0 = NEGINF;
                                            if (vv[c + 1] == 0.f) v1 = NEGINF; }
                if (EPI == EPI_ADD)       { float2 a2 = *(const float2*)(ad + (long)r * N + c);
                                            v0 += a2.x; v1 += a2.y; }
                if (EPI == EPI_BIAS_RELU) { v0 = fmaxf(v0 + vv[c], 0.f); v1 = fmaxf(v1 + vv[c + 1], 0.f); }
                if (EPI == EPI_BIAS)      { v0 += vv[c]; v1 += vv[c + 1]; }
                float2 o2 = make_float2(v0, v1);
                *(float2*)(Cm + (long)r * N + c) = o2;
            }
        }
    }
#undef LD_TILE
#undef ST_TILE
}

// ---------------- softmax over rows of length TT, times query mask ----------------
__global__ __launch_bounds__(256)
void softmax_k(float* __restrict__ S, const float* __restrict__ qmask)
{
    __shared__ float sh[8];
    const long row = blockIdx.x;
    float* p = S + row * TT;
    const int tid = threadIdx.x, lane = tid & 31, w = tid >> 5;

    float x[8];
#pragma unroll
    for (int i = 0; i < 8; i++) x[i] = p[tid + i * 256];

    float m = -3.4e38f;
#pragma unroll
    for (int i = 0; i < 8; i++) m = fmaxf(m, x[i]);
#pragma unroll
    for (int o = 16; o; o >>= 1) m = fmaxf(m, __shfl_xor_sync(0xffffffffu, m, o));
    if (lane == 0) sh[w] = m;
    __syncthreads();
#pragma unroll
    for (int i = 0; i < 8; i++) m = fmaxf(m, sh[i]);

    float s = 0.f;
#pragma unroll
    for (int i = 0; i < 8; i++) { x[i] = expf(x[i] - m); s += x[i]; }
#pragma unroll
    for (int o = 16; o; o >>= 1) s += __shfl_xor_sync(0xffffffffu, s, o);
    __syncthreads();
    if (lane == 0) sh[w] = s;
    __syncthreads();
    s = 0.f;
#pragma unroll
    for (int i = 0; i < 8; i++) s += sh[i];

    const float inv = qmask[row] / s;
#pragma unroll
    for (int i = 0; i < 8; i++) p[tid + i * 256] = x[i] * inv;
}

// ---------------- LayerNorm over rows of length CH ----------------
__global__ __launch_bounds__(256)
void ln_k(const float* __restrict__ in, float* __restrict__ out,
          const float* __restrict__ gamma, const float* __restrict__ beta)
{
    __shared__ float sh[8];
    const long row = blockIdx.x;
    const float* p = in + row * CH;
    const int tid = threadIdx.x, lane = tid & 31, w = tid >> 5;
    const int c = tid * 4;

    float4 xv = *(const float4*)(p + c);
    float s = xv.x + xv.y + xv.z + xv.w;
#pragma unroll
    for (int o = 16; o; o >>= 1) s += __shfl_xor_sync(0xffffffffu, s, o);
    if (lane == 0) sh[w] = s;
    __syncthreads();
    float tot = 0.f;
#pragma unroll
    for (int i = 0; i < 8; i++) tot += sh[i];
    const float mu = tot * (1.f / CH);

    float d0 = xv.x - mu, d1 = xv.y - mu, d2 = xv.z - mu, d3 = xv.w - mu;
    float q = d0 * d0 + d1 * d1 + d2 * d2 + d3 * d3;
#pragma unroll
    for (int o = 16; o; o >>= 1) q += __shfl_xor_sync(0xffffffffu, q, o);
    __syncthreads();
    if (lane == 0) sh[w] = q;
    __syncthreads();
    float vtot = 0.f;
#pragma unroll
    for (int i = 0; i < 8; i++) vtot += sh[i];
    const float rstd = rsqrtf(vtot * (1.f / CH) + 1e-6f);

    float4 g  = *(const float4*)(gamma + c);
    float4 be = *(const float4*)(beta + c);
    float4 o4;
    o4.x = d0 * rstd * g.x + be.x;
    o4.y = d1 * rstd * g.y + be.y;
    o4.z = d2 * rstd * g.z + be.z;
    o4.w = d3 * rstd * g.w + be.w;
    *(float4*)(out + row * CH + c) = o4;
}

// ---------------- launch ----------------
extern "C" void kernel_launch(void* const* d_in, const int* in_sizes, int n_in,
                              void* d_out, int out_size)
{
    const float* Q     = (const float*)d_in[0];
    const float* Kk    = (const float*)d_in[1];
    const float* kmask = (const float*)d_in[2];
    const float* qmask = (const float*)d_in[3];
    const float* u     = (const float*)d_in[4];
    const float* dd    = (const float*)d_in[5];
    const float* W1    = (const float*)d_in[6];
    const float* b1    = (const float*)d_in[7];
    const float* W2    = (const float*)d_in[8];
    const float* b2    = (const float*)d_in[9];
    const float* gamma = (const float*)d_in[10];
    const float* beta  = (const float*)d_in[11];

    float *f1, *f2, *S;
    cudaGetSymbolAddress((void**)&f1, g_f1);
    cudaGetSymbolAddress((void**)&f2, g_f2);
    cudaGetSymbolAddress((void**)&S,  g_S);

    const long NTC = (long)BB * TT * CH;
    float* out2 = (float*)d_out;
    if ((long)out_size >= 2 * NTC) {
        cudaMemcpyAsync(d_out, Q, NTC * sizeof(float), cudaMemcpyDeviceToDevice);
        out2 = (float*)d_out + NTC;
    }

    const dim3 blk(256);
    const long TC = (long)TT * CH;
    const long TTl = (long)TT * TT;

    // 1) f1 = relu(Q @ u) * d_diag      [16384 x 1024]
    gemm_tc<EPI_RELU_DIAG, false><<<dim3(CH / 128, BB * TT / 128, 1), blk>>>(
        Q, u, f1, BB * TT, CH, CH, 0, 0, 0, dd, 0, nullptr, 0, 0.f);

    // 2) f2 = relu(K @ u)
    gemm_tc<EPI_RELU, false><<<dim3(CH / 128, BB * TT / 128, 1), blk>>>(
        Kk, u, f2, BB * TT, CH, CH, 0, 0, 0, nullptr, 0, nullptr, 0, 0.f);

    // 3) S[b] = (f1[b] @ f2[b]^T) / 32, key-masked   [8 x 2048 x 2048]
    gemm_tc<EPI_SCORE, true><<<dim3(TT / 128, TT / 128, BB), blk>>>(
        f1, f2, S, TT, TT, CH, TC, TC, TTl, kmask, TT, nullptr, 0, 1.0f / 32.0f);

    // 4) softmax rows, * query_mask
    softmax_k<<<BB * TT, 256>>>(S, qmask);

    // 5) ctx = attn @ K + Q  -> f1
    gemm_tc<EPI_ADD, false><<<dim3(CH / 128, TT / 128, BB), blk>>>(
        S, Kk, f1, TT, CH, TT, TTl, TC, TC, nullptr, 0, Q, TC, 0.f);

    // 6) LayerNorm -> f2
    ln_k<<<BB * TT, 256>>>(f1, f2, gamma, beta);

    // 7) h = relu(f2 @ W1 + b1) -> S (reused as [16384 x 1024] scratch)
    gemm_tc<EPI_BIAS_RELU, false><<<dim3(CH / 128, BB * TT / 128, 1), blk>>>(
        f2, W1, S, BB * TT, CH, CH, 0, 0, 0, b1, 0, nullptr, 0, 0.f);

    // 8) out2 = h @ W2 + b2
    gemm_tc<EPI_BIAS, false><<<dim3(CH / 128, BB * TT / 128, 1), blk>>>(
        S, W2, out2, BB * TT, CH, CH, 0, 0, 0, b2, 0, nullptr, 0, 0.f);
}

// round 5
// speedup vs baseline: 5.4883x; 1.6969x over previous
#include <cuda_runtime.h>
#include <cuda_fp16.h>
#include <math.h>
#include <stdint.h>

#define BB  8
#define TT  2048
#define CH  1024
#define NEGINF (-4294967295.0f)

#define NTC   (BB * TT * CH)              // 16,777,216
#define NTT   ((size_t)BB * TT * TT)      // 33,554,432

// ---------------- scratch (no allocations allowed) ----------------
__device__ __half g_hQ [NTC];
__device__ __half g_hK [NTC];
__device__ __half g_hKT[NTC];             // per-batch [CH][TT]
__device__ __half g_hUT [CH * CH];
__device__ __half g_hW1T[CH * CH];
__device__ __half g_hW2T[CH * CH];
__device__ __half g_f1h[NTC];
__device__ __half g_f2h[NTC];
__device__ float  g_S  [NTT];             // fp32 scores
__device__ __half g_hS [NTT];             // f16 attn weights
__device__ float  g_ctx[NTC];             // fp32 ctx (attn@K + Q)
__device__ __half g_hLN[NTC];
__device__ __half g_hH [NTC];

enum { EPI_RELU = 0, EPI_RELU_DIAG, EPI_SCORE, EPI_ADD, EPI_BIAS_RELU, EPI_BIAS };

// ---------------- PTX helpers ----------------
__device__ __forceinline__ uint32_t smem_u32(const void* p) {
    uint32_t a;
    asm("{ .reg .u64 t; cvta.to.shared.u64 t, %1; cvt.u32.u64 %0, t; }" : "=r"(a) : "l"(p));
    return a;
}
__device__ __forceinline__ void ldsm4(uint32_t* r, uint32_t addr) {
    asm volatile("ldmatrix.sync.aligned.m8n8.x4.shared.b16 {%0,%1,%2,%3}, [%4];"
        : "=r"(r[0]), "=r"(r[1]), "=r"(r[2]), "=r"(r[3]) : "r"(addr));
}
__device__ __forceinline__ void mma_f16(float* d, const uint32_t* a, const uint32_t* b) {
    asm volatile(
        "mma.sync.aligned.m16n8k16.row.col.f32.f16.f16.f32 "
        "{%0,%1,%2,%3}, {%4,%5,%6,%7}, {%8,%9}, {%0,%1,%2,%3};"
        : "+f"(d[0]), "+f"(d[1]), "+f"(d[2]), "+f"(d[3])
        : "r"(a[0]), "r"(a[1]), "r"(a[2]), "r"(a[3]), "r"(b[0]), "r"(b[1]));
}
#define CP16(dst, src) \
    asm volatile("cp.async.cg.shared.global [%0], [%1], 16;" :: "r"(dst), "l"(src) : "memory")
#define CP_COMMIT()  asm volatile("cp.async.commit_group;" ::: "memory")
#define CP_WAIT1()   asm volatile("cp.async.wait_group 1;" ::: "memory")
#define CP_WAIT0()   asm volatile("cp.async.wait_group 0;" ::: "memory")

// swizzled offset within a tile: rows of 64B (32 halves), 16B column c (0..3)
__device__ __forceinline__ uint32_t swz(int row, int c) {
    return (uint32_t)(row * 64 + (((c) ^ ((row >> 1) & 3)) << 4));
}

// ---------------- mma.sync GEMM: C = A[M][K] * B[N][K]^T, f16 in, fp32 acc ----------------
// CTA tile 128x256, K-tile 32, 3-stage cp.async ring, 8 warps (2m x 4n) of 64x64.
#define BM 128
#define BN 256
#define BK 32
#define A_BYTES (BM * 64)                 // 8192
#define B_BYTES (BN * 64)                 // 16384
#define STG     (A_BYTES + B_BYTES)       // 24576
#define SMEM_G  (3 * STG)                 // 73728

template <int EPI, bool OUTH>
__global__ void __launch_bounds__(256, 1)
gemmv3(const __half* __restrict__ A, const __half* __restrict__ B, void* __restrict__ Cv,
       int M, int N, int K, long sA, long sB, long sC,
       const float* __restrict__ vec, long sVec,
       const float* __restrict__ add, long sAdd, float scale)
{
    extern __shared__ char smem[];
    const uint32_t sb = smem_u32(smem);
    const int tid = threadIdx.x, lane = tid & 31, warp = tid >> 5;
    const int wm = warp >> 2, wn = warp & 3;       // warp tile 64x64
    const int z = blockIdx.z;

    const __half* Ap = A + (long)z * sA + (long)(blockIdx.y * BM) * K;
    const __half* Bp = B + (long)z * sB + (long)(blockIdx.x * BN) * K;

    // cp.async staging: A 512 chunks of 16B, B 1024 chunks; 16B = 8 halves.
    uint32_t adst[2], bdst[4];
    const __half* asrc[2];
    const __half* bsrc[4];
#pragma unroll
    for (int i = 0; i < 2; i++) {
        int q = tid + i * 256, r = q >> 2, c = q & 3;
        adst[i] = swz(r, c);
        asrc[i] = Ap + (long)r * K + c * 8;
    }
#pragma unroll
    for (int i = 0; i < 4; i++) {
        int q = tid + i * 256, r = q >> 2, c = q & 3;
        bdst[i] = A_BYTES + swz(r, c);
        bsrc[i] = Bp + (long)r * K + c * 8;
    }

#define ISSUE(kt)                                                              \
    do {                                                                       \
        const uint32_t _s = sb + ((kt) % 3) * STG;                             \
        const long _ko = (long)(kt) * BK;                                      \
        _Pragma("unroll") for (int i = 0; i < 2; i++) CP16(_s + adst[i], asrc[i] + _ko); \
        _Pragma("unroll") for (int i = 0; i < 4; i++) CP16(_s + bdst[i], bsrc[i] + _ko); \
        CP_COMMIT();                                                           \
    } while (0)

    // ldmatrix lane addressing
    const int q8 = lane >> 3, rr = lane & 7;
    const int rA = wm * 64 + (q8 & 1) * 8 + rr;    // + mi*16
    const int xA = (rA >> 1) & 3;
    const int cA = q8 >> 1;                        // + 2s
    const int rB = wn * 64 + (q8 >> 1) * 8 + rr;   // + nip*16
    const int xB = (rB >> 1) & 3;
    const int cB = q8 & 1;                         // + 2s

    float acc[4][8][4];
#pragma unroll
    for (int mi = 0; mi < 4; mi++)
#pragma unroll
        for (int ni = 0; ni < 8; ni++)
#pragma unroll
            for (int e = 0; e < 4; e++) acc[mi][ni][e] = 0.f;

    ISSUE(0);
    ISSUE(1);

    const int nCh = K / BK;
    for (int kt = 0; kt < nCh; kt++) {
        if (kt + 1 < nCh) CP_WAIT1(); else CP_WAIT0();
        __syncthreads();
        const uint32_t sbase = sb + (kt % 3) * STG;

#pragma unroll
        for (int s = 0; s < 2; s++) {
            uint32_t af[4][4];
#pragma unroll
            for (int mi = 0; mi < 4; mi++)
                ldsm4(af[mi], sbase + (uint32_t)((rA + mi * 16) * 64) +
                              (uint32_t)((((2 * s + cA) ^ xA)) << 4));
#pragma unroll
            for (int nip = 0; nip < 4; nip++) {
                uint32_t t4[4];
                ldsm4(t4, sbase + A_BYTES + (uint32_t)((rB + nip * 16) * 64) +
                          (uint32_t)((((2 * s + cB) ^ xB)) << 4));
#pragma unroll
                for (int mi = 0; mi < 4; mi++) mma_f16(acc[mi][2 * nip],     af[mi], &t4[0]);
#pragma unroll
                for (int mi = 0; mi < 4; mi++) mma_f16(acc[mi][2 * nip + 1], af[mi], &t4[2]);
            }
        }
        if (kt + 2 < nCh) ISSUE(kt + 2);
    }

    // ---------------- epilogue ----------------
    const float* vv = vec ? vec + (long)z * sVec : nullptr;
    const float* adb = add ? add + (long)z * sAdd : nullptr;
    const long cBase = (long)z * sC;

#pragma unroll
    for (int mi = 0; mi < 4; mi++) {
        const int r0 = blockIdx.y * BM + wm * 64 + mi * 16 + (lane >> 2);
#pragma unroll
        for (int ni = 0; ni < 8; ni++) {
            const int c = blockIdx.x * BN + wn * 64 + ni * 8 + (lane & 3) * 2;
#pragma unroll
            for (int p = 0; p < 2; p++) {
                const int r = r0 + p * 8;
                float v0 = acc[mi][ni][p * 2 + 0];
                float v1 = acc[mi][ni][p * 2 + 1];
                if (EPI == EPI_RELU)      { v0 = fmaxf(v0, 0.f); v1 = fmaxf(v1, 0.f); }
                if (EPI == EPI_RELU_DIAG) { v0 = fmaxf(v0, 0.f) * vv[c]; v1 = fmaxf(v1, 0.f) * vv[c + 1]; }
                if (EPI == EPI_SCORE)     { v0 *= scale; v1 *= scale;
                                            if (vv[c] == 0.f)     v0 = NEGINF;
                                            if (vv[c + 1] == 0.f) v1 = NEGINF; }
                if (EPI == EPI_ADD)       { float2 a2 = *(const float2*)(adb + (long)r * N + c);
                                            v0 += a2.x; v1 += a2.y; }
                if (EPI == EPI_BIAS_RELU) { v0 = fmaxf(v0 + vv[c], 0.f); v1 = fmaxf(v1 + vv[c + 1], 0.f); }
                if (EPI == EPI_BIAS)      { v0 += vv[c]; v1 += vv[c + 1]; }
                if (OUTH) {
                    __half* op = (__half*)Cv + cBase + (long)r * N + c;
                    *(__half2*)op = __floats2half2_rn(v0, v1);
                } else {
                    float* op = (float*)Cv + cBase + (long)r * N + c;
                    *(float2*)op = make_float2(v0, v1);
                }
            }
        }
    }
#undef ISSUE
}

// ---------------- f32 -> f16 convert ----------------
__global__ __launch_bounds__(256)
void conv_k(const float* __restrict__ in, __half* __restrict__ out)
{
    const int i = blockIdx.x * 256 + threadIdx.x;
    float4 v = ((const float4*)in)[i];
    __half2* o = (__half2*)out + (long)i * 2;
    o[0] = __floats2half2_rn(v.x, v.y);
    o[1] = __floats2half2_rn(v.z, v.w);
}

// ---------------- f32 transpose -> f16:  out[C][R] = in[R][C] ----------------
__global__ __launch_bounds__(256)
void transp_k(const float* __restrict__ in, __half* __restrict__ out,
              int R, int C, long sIn, long sOut)
{
    __shared__ float t[32][33];
    const long zi = (long)blockIdx.z * sIn, zo = (long)blockIdx.z * sOut;
    const int c0 = blockIdx.x * 32, r0 = blockIdx.y * 32;
    const int tx = threadIdx.x, ty = threadIdx.y;
#pragma unroll
    for (int i = ty; i < 32; i += 8)
        t[i][tx] = in[zi + (long)(r0 + i) * C + c0 + tx];
    __syncthreads();
#pragma unroll
    for (int i = ty; i < 32; i += 8)
        out[zo + (long)(c0 + i) * R + r0 + tx] = __float2half(t[tx][i]);
}

// ---------------- softmax: fp32 S rows -> f16 attn rows (* query mask) ----------------
__global__ __launch_bounds__(256)
void softmax_k(const float* __restrict__ S, __half* __restrict__ O,
               const float* __restrict__ qmask)
{
    __shared__ float sh[8];
    const long row = blockIdx.x;
    const float* p = S + row * TT;
    __half* o = O + row * TT;
    const int tid = threadIdx.x, lane = tid & 31, w = tid >> 5;

    float x[8];
#pragma unroll
    for (int i = 0; i < 8; i++) x[i] = p[tid + i * 256];

    float m = -3.4e38f;
#pragma unroll
    for (int i = 0; i < 8; i++) m = fmaxf(m, x[i]);
#pragma unroll
    for (int off = 16; off; off >>= 1) m = fmaxf(m, __shfl_xor_sync(0xffffffffu, m, off));
    if (lane == 0) sh[w] = m;
    __syncthreads();
#pragma unroll
    for (int i = 0; i < 8; i++) m = fmaxf(m, sh[i]);

    float s = 0.f;
#pragma unroll
    for (int i = 0; i < 8; i++) { x[i] = expf(x[i] - m); s += x[i]; }
#pragma unroll
    for (int off = 16; off; off >>= 1) s += __shfl_xor_sync(0xffffffffu, s, off);
    __syncthreads();
    if (lane == 0) sh[w] = s;
    __syncthreads();
    s = 0.f;
#pragma unroll
    for (int i = 0; i < 8; i++) s += sh[i];

    const float inv = qmask[row] / s;
#pragma unroll
    for (int i = 0; i < 8; i++) o[tid + i * 256] = __float2half(x[i] * inv);
}

// ---------------- LayerNorm: fp32 in -> f16 out ----------------
__global__ __launch_bounds__(256)
void ln_k(const float* __restrict__ in, __half* __restrict__ out,
          const float* __restrict__ gamma, const float* __restrict__ beta)
{
    __shared__ float sh[8];
    const long row = blockIdx.x;
    const float* p = in + row * CH;
    const int tid = threadIdx.x, lane = tid & 31, w = tid >> 5;
    const int c = tid * 4;

    float4 xv = *(const float4*)(p + c);
    float s = xv.x + xv.y + xv.z + xv.w;
#pragma unroll
    for (int o = 16; o; o >>= 1) s += __shfl_xor_sync(0xffffffffu, s, o);
    if (lane == 0) sh[w] = s;
    __syncthreads();
    float tot = 0.f;
#pragma unroll
    for (int i = 0; i < 8; i++) tot += sh[i];
    const float mu = tot * (1.f / CH);

    float d0 = xv.x - mu, d1 = xv.y - mu, d2 = xv.z - mu, d3 = xv.w - mu;
    float q = d0 * d0 + d1 * d1 + d2 * d2 + d3 * d3;
#pragma unroll
    for (int o = 16; o; o >>= 1) q += __shfl_xor_sync(0xffffffffu, q, o);
    __syncthreads();
    if (lane == 0) sh[w] = q;
    __syncthreads();
    float vtot = 0.f;
#pragma unroll
    for (int i = 0; i < 8; i++) vtot += sh[i];
    const float rstd = rsqrtf(vtot * (1.f / CH) + 1e-6f);

    float4 g  = *(const float4*)(gamma + c);
    float4 be = *(const float4*)(beta + c);
    __half2* o2 = (__half2*)(out + row * CH + c);
    o2[0] = __floats2half2_rn(d0 * rstd * g.x + be.x, d1 * rstd * g.y + be.y);
    o2[1] = __floats2half2_rn(d2 * rstd * g.z + be.z, d3 * rstd * g.w + be.w);
}

// ---------------- launch ----------------
extern "C" void kernel_launch(void* const* d_in, const int* in_sizes, int n_in,
                              void* d_out, int out_size)
{
    const float* Q     = (const float*)d_in[0];
    const float* Kk    = (const float*)d_in[1];
    const float* kmask = (const float*)d_in[2];
    const float* qmask = (const float*)d_in[3];
    const float* u     = (const float*)d_in[4];
    const float* dd    = (const float*)d_in[5];
    const float* W1    = (const float*)d_in[6];
    const float* b1    = (const float*)d_in[7];
    const float* W2    = (const float*)d_in[8];
    const float* b2    = (const float*)d_in[9];
    const float* gamma = (const float*)d_in[10];
    const float* beta  = (const float*)d_in[11];

    __half *hQ, *hK, *hKT, *hUT, *hW1T, *hW2T, *f1h, *f2h, *hS, *hLN, *hH;
    float  *S, *ctx;
    cudaGetSymbolAddress((void**)&hQ,  g_hQ);
    cudaGetSymbolAddress((void**)&hK,  g_hK);
    cudaGetSymbolAddress((void**)&hKT, g_hKT);
    cudaGetSymbolAddress((void**)&hUT, g_hUT);
    cudaGetSymbolAddress((void**)&hW1T, g_hW1T);
    cudaGetSymbolAddress((void**)&hW2T, g_hW2T);
    cudaGetSymbolAddress((void**)&f1h, g_f1h);
    cudaGetSymbolAddress((void**)&f2h, g_f2h);
    cudaGetSymbolAddress((void**)&S,   g_S);
    cudaGetSymbolAddress((void**)&hS,  g_hS);
    cudaGetSymbolAddress((void**)&ctx, g_ctx);
    cudaGetSymbolAddress((void**)&hLN, g_hLN);
    cudaGetSymbolAddress((void**)&hH,  g_hH);

    const long TC  = (long)TT * CH;
    const long TTl = (long)TT * TT;

    float* out2 = (float*)d_out;
    if ((long)out_size >= 2 * (long)NTC) {
        cudaMemcpyAsync(d_out, Q, (long)NTC * sizeof(float), cudaMemcpyDeviceToDevice);
        out2 = (float*)d_out + NTC;
    }

    cudaFuncSetAttribute(gemmv3<EPI_RELU_DIAG, true>,  cudaFuncAttributeMaxDynamicSharedMemorySize, SMEM_G);
    cudaFuncSetAttribute(gemmv3<EPI_RELU, true>,       cudaFuncAttributeMaxDynamicSharedMemorySize, SMEM_G);
    cudaFuncSetAttribute(gemmv3<EPI_SCORE, false>,     cudaFuncAttributeMaxDynamicSharedMemorySize, SMEM_G);
    cudaFuncSetAttribute(gemmv3<EPI_ADD, false>,       cudaFuncAttributeMaxDynamicSharedMemorySize, SMEM_G);
    cudaFuncSetAttribute(gemmv3<EPI_BIAS_RELU, true>,  cudaFuncAttributeMaxDynamicSharedMemorySize, SMEM_G);
    cudaFuncSetAttribute(gemmv3<EPI_BIAS, false>,      cudaFuncAttributeMaxDynamicSharedMemorySize, SMEM_G);

    // ---- conversions ----
    conv_k<<<NTC / 1024, 256>>>(Q,  hQ);
    conv_k<<<NTC / 1024, 256>>>(Kk, hK);
    transp_k<<<dim3(CH / 32, CH / 32, 1), dim3(32, 8)>>>(u,  hUT,  CH, CH, 0, 0);
    transp_k<<<dim3(CH / 32, CH / 32, 1), dim3(32, 8)>>>(W1, hW1T, CH, CH, 0, 0);
    transp_k<<<dim3(CH / 32, CH / 32, 1), dim3(32, 8)>>>(W2, hW2T, CH, CH, 0, 0);
    transp_k<<<dim3(CH / 32, TT / 32, BB), dim3(32, 8)>>>(Kk, hKT, TT, CH, TC, TC);

    // ---- 1) f1 = relu(Q @ u) * d_diag ----
    gemmv3<EPI_RELU_DIAG, true><<<dim3(CH / BN, BB * TT / BM, 1), 256, SMEM_G>>>(
        hQ, hUT, f1h, BB * TT, CH, CH, 0, 0, 0, dd, 0, nullptr, 0, 0.f);

    // ---- 2) f2 = relu(K @ u) ----
    gemmv3<EPI_RELU, true><<<dim3(CH / BN, BB * TT / BM, 1), 256, SMEM_G>>>(
        hK, hUT, f2h, BB * TT, CH, CH, 0, 0, 0, nullptr, 0, nullptr, 0, 0.f);

    // ---- 3) S = (f1 @ f2^T)/32, key-masked (fp32) ----
    gemmv3<EPI_SCORE, false><<<dim3(TT / BN, TT / BM, BB), 256, SMEM_G>>>(
        f1h, f2h, S, TT, TT, CH, TC, TC, TTl, kmask, TT, nullptr, 0, 1.0f / 32.0f);

    // ---- 4) softmax -> f16 attn ----
    softmax_k<<<BB * TT, 256>>>(S, hS, qmask);

    // ---- 5) ctx = attn @ K + Q (fp32) ----
    gemmv3<EPI_ADD, false><<<dim3(CH / BN, TT / BM, BB), 256, SMEM_G>>>(
        hS, hKT, ctx, TT, CH, TT, TTl, TC, TC, nullptr, 0, Q, TC, 0.f);

    // ---- 6) LayerNorm -> f16 ----
    ln_k<<<BB * TT, 256>>>(ctx, hLN, gamma, beta);

    // ---- 7) h = relu(LN @ W1 + b1) -> f16 ----
    gemmv3<EPI_BIAS_RELU, true><<<dim3(CH / BN, BB * TT / BM, 1), 256, SMEM_G>>>(
        hLN, hW1T, hH, BB * TT, CH, CH, 0, 0, 0, b1, 0, nullptr, 0, 0.f);

    // ---- 8) out2 = h @ W2 + b2 (fp32) ----
    gemmv3<EPI_BIAS, false><<<dim3(CH / BN, BB * TT / BM, 1), 256, SMEM_G>>>(
        hH, hW2T, out2, BB * TT, CH, CH, 0, 0, 0, b2, 0, nullptr, 0, 0.f);
}

// round 6
// speedup vs baseline: 5.6063x; 1.0215x over previous
#include <cuda_runtime.h>
#include <cuda_fp16.h>
#include <math.h>
#include <stdint.h>

#define BB  8
#define TT  2048
#define CH  1024
#define NEGINF_H (-60000.0f)

#define NTC   (BB * TT * CH)              // 16,777,216
#define NTT   ((size_t)BB * TT * TT)      // 33,554,432

// ---------------- scratch (no allocations allowed) ----------------
__device__ __half g_hQ [NTC];
__device__ __half g_hK [NTC];
__device__ __half g_hKT[NTC];             // per-batch [CH][TT]
__device__ __half g_hUT [CH * CH];
__device__ __half g_hW1T[CH * CH];
__device__ __half g_hW2T[CH * CH];
__device__ __half g_f1h[NTC];
__device__ __half g_f2h[NTC];
__device__ __half g_hS [NTT];             // f16 scores / attn weights (in-place softmax)
__device__ float  g_ctx[NTC];             // fp32 ctx (attn@K + Q)
__device__ __half g_hLN[NTC];
__device__ __half g_hH [NTC];

enum { EPI_RELU = 0, EPI_RELU_DIAG, EPI_SCORE, EPI_ADD, EPI_BIAS_RELU, EPI_BIAS };

// ---------------- PTX helpers ----------------
__device__ __forceinline__ uint32_t smem_u32(const void* p) {
    uint32_t a;
    asm("{ .reg .u64 t; cvta.to.shared.u64 t, %1; cvt.u32.u64 %0, t; }" : "=r"(a) : "l"(p));
    return a;
}
__device__ __forceinline__ void ldsm4(uint32_t* r, uint32_t addr) {
    asm volatile("ldmatrix.sync.aligned.m8n8.x4.shared.b16 {%0,%1,%2,%3}, [%4];"
        : "=r"(r[0]), "=r"(r[1]), "=r"(r[2]), "=r"(r[3]) : "r"(addr));
}
__device__ __forceinline__ void mma_f16(float* d, const uint32_t* a, const uint32_t* b) {
    asm volatile(
        "mma.sync.aligned.m16n8k16.row.col.f32.f16.f16.f32 "
        "{%0,%1,%2,%3}, {%4,%5,%6,%7}, {%8,%9}, {%0,%1,%2,%3};"
        : "+f"(d[0]), "+f"(d[1]), "+f"(d[2]), "+f"(d[3])
        : "r"(a[0]), "r"(a[1]), "r"(a[2]), "r"(a[3]), "r"(b[0]), "r"(b[1]));
}
#define CP16(dst, src) \
    asm volatile("cp.async.cg.shared.global [%0], [%1], 16;" :: "r"(dst), "l"(src) : "memory")
#define CP_COMMIT()  asm volatile("cp.async.commit_group;" ::: "memory")
#define CP_WAIT1()   asm volatile("cp.async.wait_group 1;" ::: "memory")
#define CP_WAIT0()   asm volatile("cp.async.wait_group 0;" ::: "memory")

// swizzled offset within a tile: rows of 64B (32 halves), 16B column c (0..3)
__device__ __forceinline__ uint32_t swz(int row, int c) {
    return (uint32_t)(row * 64 + (((c) ^ ((row >> 1) & 3)) << 4));
}

// ---------------- mma.sync GEMM: C = A[M][K] * B[N][K]^T, f16 in, fp32 acc ----------------
// CTA tile 128x256, K-tile 32, 3-stage cp.async ring, 16 warps (4m x 4n) of 32x64.
#define BM 128
#define BN 256
#define BK 32
#define A_BYTES (BM * 64)                 // 8192
#define B_BYTES (BN * 64)                 // 16384
#define STG     (A_BYTES + B_BYTES)       // 24576
#define SMEM_G  (3 * STG)                 // 73728
#define NTHR    512

template <int EPI, bool OUTH>
__global__ void __launch_bounds__(NTHR, 1)
gemmv4(const __half* __restrict__ A, const __half* __restrict__ B, void* __restrict__ Cv,
       int M, int N, int K, long sA, long sB, long sC,
       const float* __restrict__ vec, long sVec,
       const float* __restrict__ add, long sAdd, float scale)
{
    extern __shared__ char smem[];
    const uint32_t sb = smem_u32(smem);
    const int tid = threadIdx.x, lane = tid & 31, warp = tid >> 5;
    const int wm = warp >> 2, wn = warp & 3;       // warp tile 32x64
    const int z = blockIdx.z;

    const __half* Ap = A + (long)z * sA + (long)(blockIdx.y * BM) * K;
    const __half* Bp = B + (long)z * sB + (long)(blockIdx.x * BN) * K;

    // cp.async staging: A 512 chunks of 16B (1/thread), B 1024 chunks (2/thread).
    uint32_t adst, bdst[2];
    const __half* asrc;
    const __half* bsrc[2];
    {
        int r = tid >> 2, c = tid & 3;
        adst = swz(r, c);
        asrc = Ap + (long)r * K + c * 8;
    }
#pragma unroll
    for (int i = 0; i < 2; i++) {
        int q = tid + i * NTHR, r = q >> 2, c = q & 3;
        bdst[i] = A_BYTES + swz(r, c);
        bsrc[i] = Bp + (long)r * K + c * 8;
    }

#define ISSUE(kt)                                                              \
    do {                                                                       \
        const uint32_t _s = sb + ((kt) % 3) * STG;                             \
        const long _ko = (long)(kt) * BK;                                      \
        CP16(_s + adst, asrc + _ko);                                           \
        CP16(_s + bdst[0], bsrc[0] + _ko);                                     \
        CP16(_s + bdst[1], bsrc[1] + _ko);                                     \
        CP_COMMIT();                                                           \
    } while (0)

    // ldmatrix lane addressing
    const int q8 = lane >> 3, rr = lane & 7;
    const int rA = wm * 32 + (q8 & 1) * 8 + rr;    // + mi*16
    const int xA = (rA >> 1) & 3;
    const int cA = q8 >> 1;                        // + 2s
    const int rB = wn * 64 + (q8 >> 1) * 8 + rr;   // + nip*16
    const int xB = (rB >> 1) & 3;
    const int cB = q8 & 1;                         // + 2s

    float acc[2][8][4];
#pragma unroll
    for (int mi = 0; mi < 2; mi++)
#pragma unroll
        for (int ni = 0; ni < 8; ni++)
#pragma unroll
            for (int e = 0; e < 4; e++) acc[mi][ni][e] = 0.f;

    ISSUE(0);
    ISSUE(1);

    const int nCh = K / BK;
    for (int kt = 0; kt < nCh; kt++) {
        if (kt + 1 < nCh) CP_WAIT1(); else CP_WAIT0();
        __syncthreads();
        const uint32_t sbase = sb + (kt % 3) * STG;

#pragma unroll
        for (int s = 0; s < 2; s++) {
            uint32_t af[2][4];
#pragma unroll
            for (int mi = 0; mi < 2; mi++)
                ldsm4(af[mi], sbase + (uint32_t)((rA + mi * 16) * 64) +
                              (uint32_t)((((2 * s + cA) ^ xA)) << 4));
#pragma unroll
            for (int nip = 0; nip < 4; nip++) {
                uint32_t t4[4];
                ldsm4(t4, sbase + A_BYTES + (uint32_t)((rB + nip * 16) * 64) +
                          (uint32_t)((((2 * s + cB) ^ xB)) << 4));
#pragma unroll
                for (int mi = 0; mi < 2; mi++) mma_f16(acc[mi][2 * nip],     af[mi], &t4[0]);
#pragma unroll
                for (int mi = 0; mi < 2; mi++) mma_f16(acc[mi][2 * nip + 1], af[mi], &t4[2]);
            }
        }
        if (kt + 2 < nCh) ISSUE(kt + 2);
    }

    // ---------------- epilogue ----------------
    const float* vv = vec ? vec + (long)z * sVec : nullptr;
    const float* adb = add ? add + (long)z * sAdd : nullptr;
    const long cBase = (long)z * sC;

#pragma unroll
    for (int mi = 0; mi < 2; mi++) {
        const int r0 = blockIdx.y * BM + wm * 32 + mi * 16 + (lane >> 2);
#pragma unroll
        for (int ni = 0; ni < 8; ni++) {
            const int c = blockIdx.x * BN + wn * 64 + ni * 8 + (lane & 3) * 2;
#pragma unroll
            for (int p = 0; p < 2; p++) {
                const int r = r0 + p * 8;
                float v0 = acc[mi][ni][p * 2 + 0];
                float v1 = acc[mi][ni][p * 2 + 1];
                if (EPI == EPI_RELU)      { v0 = fmaxf(v0, 0.f); v1 = fmaxf(v1, 0.f); }
                if (EPI == EPI_RELU_DIAG) { v0 = fmaxf(v0, 0.f) * vv[c]; v1 = fmaxf(v1, 0.f) * vv[c + 1]; }
                if (EPI == EPI_SCORE)     { v0 *= scale; v1 *= scale;
                                            if (vv[c] == 0.f)     v0 = NEGINF_H;
                                            if (vv[c + 1] == 0.f) v1 = NEGINF_H; }
                if (EPI == EPI_ADD)       { float2 a2 = *(const float2*)(adb + (long)r * N + c);
                                            v0 += a2.x; v1 += a2.y; }
                if (EPI == EPI_BIAS_RELU) { v0 = fmaxf(v0 + vv[c], 0.f); v1 = fmaxf(v1 + vv[c + 1], 0.f); }
                if (EPI == EPI_BIAS)      { v0 += vv[c]; v1 += vv[c + 1]; }
                if (OUTH) {
                    __half* op = (__half*)Cv + cBase + (long)r * N + c;
                    *(__half2*)op = __floats2half2_rn(v0, v1);
                } else {
                    float* op = (float*)Cv + cBase + (long)r * N + c;
                    *(float2*)op = make_float2(v0, v1);
                }
            }
        }
    }
#undef ISSUE
}

// ---------------- Q convert: f32 -> f16, plus fp32 copy to output ----------------
__global__ __launch_bounds__(256)
void convq_k(const float* __restrict__ in, __half* __restrict__ out, float* __restrict__ outc)
{
    const int i = blockIdx.x * 256 + threadIdx.x;
    float4 v = ((const float4*)in)[i];
    __half2* o = (__half2*)out + (long)i * 2;
    o[0] = __floats2half2_rn(v.x, v.y);
    o[1] = __floats2half2_rn(v.z, v.w);
    ((float4*)outc)[i] = v;
}

// ---------------- K convert + transpose: f32 [R][C] -> f16 linear + f16 [C][R] ----------------
__global__ __launch_bounds__(256)
void convkt_k(const float* __restrict__ in, __half* __restrict__ lin, __half* __restrict__ tr,
              int R, int C, long sIn, long sOut)
{
    __shared__ float t[32][33];
    const long zi = (long)blockIdx.z * sIn, zo = (long)blockIdx.z * sOut;
    const int c0 = blockIdx.x * 32, r0 = blockIdx.y * 32;
    const int tx = threadIdx.x, ty = threadIdx.y;
#pragma unroll
    for (int i = ty; i < 32; i += 8) {
        float v = in[zi + (long)(r0 + i) * C + c0 + tx];
        t[i][tx] = v;
        lin[zi + (long)(r0 + i) * C + c0 + tx] = __float2half(v);
    }
    __syncthreads();
#pragma unroll
    for (int i = ty; i < 32; i += 8)
        tr[zo + (long)(c0 + i) * R + r0 + tx] = __float2half(t[tx][i]);
}

// ---------------- f32 transpose -> f16 (square weights) ----------------
__global__ __launch_bounds__(256)
void transp_k(const float* __restrict__ in, __half* __restrict__ out, int R, int C)
{
    __shared__ float t[32][33];
    const int c0 = blockIdx.x * 32, r0 = blockIdx.y * 32;
    const int tx = threadIdx.x, ty = threadIdx.y;
#pragma unroll
    for (int i = ty; i < 32; i += 8)
        t[i][tx] = in[(long)(r0 + i) * C + c0 + tx];
    __syncthreads();
#pragma unroll
    for (int i = ty; i < 32; i += 8)
        out[(long)(c0 + i) * R + r0 + tx] = __float2half(t[tx][i]);
}

// ---------------- softmax on f16 rows (in-place), * query mask ----------------
__global__ __launch_bounds__(256)
void softmax_k(__half* __restrict__ S, const float* __restrict__ qmask)
{
    __shared__ float sh[8];
    const long row = blockIdx.x;
    __half2* p = (__half2*)(S + row * TT);
    const int tid = threadIdx.x, lane = tid & 31, w = tid >> 5;

    float2 x[4];
#pragma unroll
    for (int i = 0; i < 4; i++) x[i] = __half22float2(p[tid + i * 256]);

    float m = -3.4e38f;
#pragma unroll
    for (int i = 0; i < 4; i++) m = fmaxf(m, fmaxf(x[i].x, x[i].y));
#pragma unroll
    for (int off = 16; off; off >>= 1) m = fmaxf(m, __shfl_xor_sync(0xffffffffu, m, off));
    if (lane == 0) sh[w] = m;
    __syncthreads();
#pragma unroll
    for (int i = 0; i < 8; i++) m = fmaxf(m, sh[i]);

    float s = 0.f;
#pragma unroll
    for (int i = 0; i < 4; i++) {
        x[i].x = expf(x[i].x - m); x[i].y = expf(x[i].y - m);
        s += x[i].x + x[i].y;
    }
#pragma unroll
    for (int off = 16; off; off >>= 1) s += __shfl_xor_sync(0xffffffffu, s, off);
    __syncthreads();
    if (lane == 0) sh[w] = s;
    __syncthreads();
    s = 0.f;
#pragma unroll
    for (int i = 0; i < 8; i++) s += sh[i];

    const float inv = qmask[row] / s;
#pragma unroll
    for (int i = 0; i < 4; i++)
        p[tid + i * 256] = __floats2half2_rn(x[i].x * inv, x[i].y * inv);
}

// ---------------- LayerNorm: fp32 in -> f16 out ----------------
__global__ __launch_bounds__(256)
void ln_k(const float* __restrict__ in, __half* __restrict__ out,
          const float* __restrict__ gamma, const float* __restrict__ beta)
{
    __shared__ float sh[8];
    const long row = blockIdx.x;
    const float* p = in + row * CH;
    const int tid = threadIdx.x, lane = tid & 31, w = tid >> 5;
    const int c = tid * 4;

    float4 xv = *(const float4*)(p + c);
    float s = xv.x + xv.y + xv.z + xv.w;
#pragma unroll
    for (int o = 16; o; o >>= 1) s += __shfl_xor_sync(0xffffffffu, s, o);
    if (lane == 0) sh[w] = s;
    __syncthreads();
    float tot = 0.f;
#pragma unroll
    for (int i = 0; i < 8; i++) tot += sh[i];
    const float mu = tot * (1.f / CH);

    float d0 = xv.x - mu, d1 = xv.y - mu, d2 = xv.z - mu, d3 = xv.w - mu;
    float q = d0 * d0 + d1 * d1 + d2 * d2 + d3 * d3;
#pragma unroll
    for (int o = 16; o; o >>= 1) q += __shfl_xor_sync(0xffffffffu, q, o);
    __syncthreads();
    if (lane == 0) sh[w] = q;
    __syncthreads();
    float vtot = 0.f;
#pragma unroll
    for (int i = 0; i < 8; i++) vtot += sh[i];
    const float rstd = rsqrtf(vtot * (1.f / CH) + 1e-6f);

    float4 g  = *(const float4*)(gamma + c);
    float4 be = *(const float4*)(beta + c);
    __half2* o2 = (__half2*)(out + row * CH + c);
    o2[0] = __floats2half2_rn(d0 * rstd * g.x + be.x, d1 * rstd * g.y + be.y);
    o2[1] = __floats2half2_rn(d2 * rstd * g.z + be.z, d3 * rstd * g.w + be.w);
}

// ---------------- launch ----------------
extern "C" void kernel_launch(void* const* d_in, const int* in_sizes, int n_in,
                              void* d_out, int out_size)
{
    const float* Q     = (const float*)d_in[0];
    const float* Kk    = (const float*)d_in[1];
    const float* kmask = (const float*)d_in[2];
    const float* qmask = (const float*)d_in[3];
    const float* u     = (const float*)d_in[4];
    const float* dd    = (const float*)d_in[5];
    const float* W1    = (const float*)d_in[6];
    const float* b1    = (const float*)d_in[7];
    const float* W2    = (const float*)d_in[8];
    const float* b2    = (const float*)d_in[9];
    const float* gamma = (const float*)d_in[10];
    const float* beta  = (const float*)d_in[11];

    __half *hQ, *hK, *hKT, *hUT, *hW1T, *hW2T, *f1h, *f2h, *hS, *hLN, *hH;
    float  *ctx;
    cudaGetSymbolAddress((void**)&hQ,  g_hQ);
    cudaGetSymbolAddress((void**)&hK,  g_hK);
    cudaGetSymbolAddress((void**)&hKT, g_hKT);
    cudaGetSymbolAddress((void**)&hUT, g_hUT);
    cudaGetSymbolAddress((void**)&hW1T, g_hW1T);
    cudaGetSymbolAddress((void**)&hW2T, g_hW2T);
    cudaGetSymbolAddress((void**)&f1h, g_f1h);
    cudaGetSymbolAddress((void**)&f2h, g_f2h);
    cudaGetSymbolAddress((void**)&hS,  g_hS);
    cudaGetSymbolAddress((void**)&ctx, g_ctx);
    cudaGetSymbolAddress((void**)&hLN, g_hLN);
    cudaGetSymbolAddress((void**)&hH,  g_hH);

    const long TC  = (long)TT * CH;
    const long TTl = (long)TT * TT;

    float* out2 = (float*)d_out;
    float* outq = (float*)d_out;
    if ((long)out_size >= 2 * (long)NTC) out2 = (float*)d_out + NTC;

    cudaFuncSetAttribute(gemmv4<EPI_RELU_DIAG, true>,  cudaFuncAttributeMaxDynamicSharedMemorySize, SMEM_G);
    cudaFuncSetAttribute(gemmv4<EPI_RELU, true>,       cudaFuncAttributeMaxDynamicSharedMemorySize, SMEM_G);
    cudaFuncSetAttribute(gemmv4<EPI_SCORE, true>,      cudaFuncAttributeMaxDynamicSharedMemorySize, SMEM_G);
    cudaFuncSetAttribute(gemmv4<EPI_ADD, false>,       cudaFuncAttributeMaxDynamicSharedMemorySize, SMEM_G);
    cudaFuncSetAttribute(gemmv4<EPI_BIAS_RELU, true>,  cudaFuncAttributeMaxDynamicSharedMemorySize, SMEM_G);
    cudaFuncSetAttribute(gemmv4<EPI_BIAS, false>,      cudaFuncAttributeMaxDynamicSharedMemorySize, SMEM_G);

    // ---- conversions (ordered so the 6th kernel launch is a GEMM for ncu -s 5) ----
    convq_k<<<NTC / 1024, 256>>>(Q, hQ, outq);                                   // 1
    transp_k<<<dim3(CH / 32, CH / 32), dim3(32, 8)>>>(u,  hUT,  CH, CH);         // 2
    transp_k<<<dim3(CH / 32, CH / 32), dim3(32, 8)>>>(W1, hW1T, CH, CH);         // 3
    transp_k<<<dim3(CH / 32, CH / 32), dim3(32, 8)>>>(W2, hW2T, CH, CH);         // 4
    convkt_k<<<dim3(CH / 32, TT / 32, BB), dim3(32, 8)>>>(Kk, hK, hKT, TT, CH, TC, TC); // 5

    // ---- 1) f1 = relu(Q @ u) * d_diag ----                                       6 (profiled)
    gemmv4<EPI_RELU_DIAG, true><<<dim3(CH / BN, BB * TT / BM, 1), NTHR, SMEM_G>>>(
        hQ, hUT, f1h, BB * TT, CH, CH, 0, 0, 0, dd, 0, nullptr, 0, 0.f);

    // ---- 2) f2 = relu(K @ u) ----
    gemmv4<EPI_RELU, true><<<dim3(CH / BN, BB * TT / BM, 1), NTHR, SMEM_G>>>(
        hK, hUT, f2h, BB * TT, CH, CH, 0, 0, 0, nullptr, 0, nullptr, 0, 0.f);

    // ---- 3) S = (f1 @ f2^T)/32, key-masked (f16 out) ----
    gemmv4<EPI_SCORE, true><<<dim3(TT / BN, TT / BM, BB), NTHR, SMEM_G>>>(
        f1h, f2h, hS, TT, TT, CH, TC, TC, TTl, kmask, TT, nullptr, 0, 1.0f / 32.0f);

    // ---- 4) softmax in-place on f16 ----
    softmax_k<<<BB * TT, 256>>>(hS, qmask);

    // ---- 5) ctx = attn @ K + Q (fp32) ----
    gemmv4<EPI_ADD, false><<<dim3(CH / BN, TT / BM, BB), NTHR, SMEM_G>>>(
        hS, hKT, ctx, TT, CH, TT, TTl, TC, TC, nullptr, 0, Q, TC, 0.f);

    // ---- 6) LayerNorm -> f16 ----
    ln_k<<<BB * TT, 256>>>(ctx, hLN, gamma, beta);

    // ---- 7) h = relu(LN @ W1 + b1) -> f16 ----
    gemmv4<EPI_BIAS_RELU, true><<<dim3(CH / BN, BB * TT / BM, 1), NTHR, SMEM_G>>>(
        hLN, hW1T, hH, BB * TT, CH, CH, 0, 0, 0, b1, 0, nullptr, 0, 0.f);

    // ---- 8) out2 = h @ W2 + b2 (fp32) ----
    gemmv4<EPI_BIAS, false><<<dim3(CH / BN, BB * TT / BM, 1), NTHR, SMEM_G>>>(
        hH, hW2T, out2, BB * TT, CH, CH, 0, 0, 0, b2, 0, nullptr, 0, 0.f);
}

// round 7
// speedup vs baseline: 5.8416x; 1.0420x over previous
#include <cuda_runtime.h>
#include <cuda_fp16.h>
#include <math.h>
#include <stdint.h>

#define BB  8
#define TT  2048
#define CH  1024

#define NTC   (BB * TT * CH)              // 16,777,216
#define NTT   ((size_t)BB * TT * TT)      // 33,554,432

// ---------------- scratch (no allocations allowed) ----------------
__device__ __half g_hQ [NTC];
__device__ __half g_hK [NTC];
__device__ __half g_hKT[NTC];             // per-batch [CH][TT]
__device__ __half g_hUT [CH * CH];
__device__ __half g_hW1T[CH * CH];
__device__ __half g_hW2T[CH * CH];
__device__ __half g_f1h[NTC];
__device__ __half g_f2h[NTC];
__device__ __half g_hS [NTT];             // f16 exp(scores)
__device__ float  g_part[BB * TT * 8];    // per-CTA-column row partial sums
__device__ float  g_invs[BB * TT];        // qmask/rowsum
__device__ float  g_ctx[NTC];             // fp32 ctx (attn@K + Q)
__device__ __half g_hLN[NTC];
__device__ __half g_hH [NTC];

enum { EPI_PROJ = 0, EPI_EXP, EPI_CTX, EPI_BIAS_RELU, EPI_BIAS };

// ---------------- PTX helpers ----------------
__device__ __forceinline__ uint32_t smem_u32(const void* p) {
    uint32_t a;
    asm("{ .reg .u64 t; cvta.to.shared.u64 t, %1; cvt.u32.u64 %0, t; }" : "=r"(a) : "l"(p));
    return a;
}
__device__ __forceinline__ void ldsm4(uint32_t* r, uint32_t addr) {
    asm volatile("ldmatrix.sync.aligned.m8n8.x4.shared.b16 {%0,%1,%2,%3}, [%4];"
        : "=r"(r[0]), "=r"(r[1]), "=r"(r[2]), "=r"(r[3]) : "r"(addr));
}
__device__ __forceinline__ void mma_f16(float* d, const uint32_t* a, const uint32_t* b) {
    asm volatile(
        "mma.sync.aligned.m16n8k16.row.col.f32.f16.f16.f32 "
        "{%0,%1,%2,%3}, {%4,%5,%6,%7}, {%8,%9}, {%0,%1,%2,%3};"
        : "+f"(d[0]), "+f"(d[1]), "+f"(d[2]), "+f"(d[3])
        : "r"(a[0]), "r"(a[1]), "r"(a[2]), "r"(a[3]), "r"(b[0]), "r"(b[1]));
}
#define CP16(dst, src) \
    asm volatile("cp.async.cg.shared.global [%0], [%1], 16;" :: "r"(dst), "l"(src) : "memory")
#define CP_COMMIT()  asm volatile("cp.async.commit_group;" ::: "memory")
#define CP_WAIT1()   asm volatile("cp.async.wait_group 1;" ::: "memory")
#define CP_WAIT0()   asm volatile("cp.async.wait_group 0;" ::: "memory")

// swizzled offset within a tile: rows of 64B (32 halves), 16B column c (0..3)
__device__ __forceinline__ uint32_t swz(int row, int c) {
    return (uint32_t)(row * 64 + (((c) ^ ((row >> 1) & 3)) << 4));
}

// ---------------- mma.sync GEMM: C = A[M][K] * B[N][K]^T, f16 in, fp32 acc ----------------
// CTA tile 128x256, K-tile 32, 3-stage cp.async ring, 16 warps (4m x 4n) of 32x64.
#define BM 128
#define BN 256
#define BK 32
#define A_BYTES (BM * 64)                 // 8192
#define B_BYTES (BN * 64)                 // 16384
#define STG     (A_BYTES + B_BYTES)       // 24576
#define SMEM_G  (3 * STG)                 // 73728
#define NTHR    512

template <int EPI, bool OUTH>
__global__ void __launch_bounds__(NTHR, 1)
gemmv5(const __half* __restrict__ A, const __half* __restrict__ A2,
       const __half* __restrict__ B, void* __restrict__ Cv, void* __restrict__ Cv2,
       int M, int N, int K, long sA, long sB, long sC,
       const float* __restrict__ vec, long sVec,
       const float* __restrict__ add, long sAdd, float scale,
       float* __restrict__ part)
{
    extern __shared__ char smem[];
    const uint32_t sb = smem_u32(smem);
    const int tid = threadIdx.x, lane = tid & 31, warp = tid >> 5;
    const int wm = warp >> 2, wn = warp & 3;       // warp tile 32x64
    const int z = blockIdx.z;

    const __half* Abase = A;
    void* Cbase = Cv;
    if (EPI == EPI_PROJ && z == 1) { Abase = A2; Cbase = Cv2; }

    const __half* Ap = Abase + (long)z * sA + (long)(blockIdx.y * BM) * K;
    const __half* Bp = B + (long)z * sB + (long)(blockIdx.x * BN) * K;

    // cp.async staging: A 512 chunks of 16B (1/thread), B 1024 chunks (2/thread).
    uint32_t adst, bdst[2];
    const __half* asrc;
    const __half* bsrc[2];
    {
        int r = tid >> 2, c = tid & 3;
        adst = swz(r, c);
        asrc = Ap + (long)r * K + c * 8;
    }
#pragma unroll
    for (int i = 0; i < 2; i++) {
        int q = tid + i * NTHR, r = q >> 2, c = q & 3;
        bdst[i] = A_BYTES + swz(r, c);
        bsrc[i] = Bp + (long)r * K + c * 8;
    }

#define ISSUE(kt)                                                              \
    do {                                                                       \
        const uint32_t _s = sb + ((kt) % 3) * STG;                             \
        const long _ko = (long)(kt) * BK;                                      \
        CP16(_s + adst, asrc + _ko);                                           \
        CP16(_s + bdst[0], bsrc[0] + _ko);                                     \
        CP16(_s + bdst[1], bsrc[1] + _ko);                                     \
        CP_COMMIT();                                                           \
    } while (0)

    // ldmatrix lane addressing
    const int q8 = lane >> 3, rr = lane & 7;
    const int rA = wm * 32 + (q8 & 1) * 8 + rr;    // + mi*16
    const int xA = (rA >> 1) & 3;
    const int cA = q8 >> 1;                        // + 2s
    const int rB = wn * 64 + (q8 >> 1) * 8 + rr;   // + nip*16
    const int xB = (rB >> 1) & 3;
    const int cB = q8 & 1;                         // + 2s

    float acc[2][8][4];
#pragma unroll
    for (int mi = 0; mi < 2; mi++)
#pragma unroll
        for (int ni = 0; ni < 8; ni++)
#pragma unroll
            for (int e = 0; e < 4; e++) acc[mi][ni][e] = 0.f;

    ISSUE(0);
    ISSUE(1);

    const int nCh = K / BK;
    for (int kt = 0; kt < nCh; kt++) {
        if (kt + 1 < nCh) CP_WAIT1(); else CP_WAIT0();
        __syncthreads();
        const uint32_t sbase = sb + (kt % 3) * STG;

#pragma unroll
        for (int s = 0; s < 2; s++) {
            uint32_t af[2][4];
#pragma unroll
            for (int mi = 0; mi < 2; mi++)
                ldsm4(af[mi], sbase + (uint32_t)((rA + mi * 16) * 64) +
                              (uint32_t)((((2 * s + cA) ^ xA)) << 4));
#pragma unroll
            for (int nip = 0; nip < 4; nip++) {
                uint32_t t4[4];
                ldsm4(t4, sbase + A_BYTES + (uint32_t)((rB + nip * 16) * 64) +
                          (uint32_t)((((2 * s + cB) ^ xB)) << 4));
#pragma unroll
                for (int mi = 0; mi < 2; mi++) mma_f16(acc[mi][2 * nip],     af[mi], &t4[0]);
#pragma unroll
                for (int mi = 0; mi < 2; mi++) mma_f16(acc[mi][2 * nip + 1], af[mi], &t4[2]);
            }
        }
        if (kt + 2 < nCh) ISSUE(kt + 2);
    }

    // ---------------- epilogue ----------------
    const float* vv = vec ? vec + (long)z * sVec : nullptr;
    const long cBase = (long)z * sC;

    if (EPI == EPI_EXP) {
        // exp(scale*s) (masked -> 0), write f16, accumulate per-row sums.
        float rsl[2][2] = {{0.f, 0.f}, {0.f, 0.f}};
#pragma unroll
        for (int mi = 0; mi < 2; mi++) {
            const int r0 = blockIdx.y * BM + wm * 32 + mi * 16 + (lane >> 2);
#pragma unroll
            for (int ni = 0; ni < 8; ni++) {
                const int c = blockIdx.x * BN + wn * 64 + ni * 8 + (lane & 3) * 2;
                const float m0 = vv[c], m1 = vv[c + 1];
#pragma unroll
                for (int p = 0; p < 2; p++) {
                    const int r = r0 + p * 8;
                    float e0 = (m0 == 0.f) ? 0.f : expf(acc[mi][ni][p * 2 + 0] * scale);
                    float e1 = (m1 == 0.f) ? 0.f : expf(acc[mi][ni][p * 2 + 1] * scale);
                    __half2 h = __floats2half2_rn(e0, e1);
                    *(__half2*)((__half*)Cv + cBase + (long)r * N + c) = h;
                    float2 fr = __half22float2(h);
                    rsl[mi][p] += fr.x + fr.y;
                }
            }
        }
        // reduce over the 4 lanes of each quad (columns of the row)
        float* rsf = (float*)(smem + (nCh % 3) * STG);   // stage buffer not in use
#pragma unroll
        for (int mi = 0; mi < 2; mi++)
#pragma unroll
            for (int p = 0; p < 2; p++) {
                float s = rsl[mi][p];
                s += __shfl_xor_sync(0xffffffffu, s, 1);
                s += __shfl_xor_sync(0xffffffffu, s, 2);
                if ((lane & 3) == 0)
                    rsf[(wm * 32 + mi * 16 + p * 8 + (lane >> 2)) * 4 + wn] = s;
            }
        __syncthreads();
        if (tid < BM) {
            float s = rsf[tid * 4] + rsf[tid * 4 + 1] + rsf[tid * 4 + 2] + rsf[tid * 4 + 3];
            part[((long)z * TT + blockIdx.y * BM + tid) * 8 + blockIdx.x] = s;
        }
        return;
    }

    const float* adb = add ? add + (long)z * sAdd : nullptr;

#pragma unroll
    for (int mi = 0; mi < 2; mi++) {
        const int r0 = blockIdx.y * BM + wm * 32 + mi * 16 + (lane >> 2);
        float rowS[2];
        if (EPI == EPI_CTX) { rowS[0] = vv[r0]; rowS[1] = vv[r0 + 8]; }
#pragma unroll
        for (int ni = 0; ni < 8; ni++) {
            const int c = blockIdx.x * BN + wn * 64 + ni * 8 + (lane & 3) * 2;
#pragma unroll
            for (int p = 0; p < 2; p++) {
                const int r = r0 + p * 8;
                float v0 = acc[mi][ni][p * 2 + 0];
                float v1 = acc[mi][ni][p * 2 + 1];
                if (EPI == EPI_PROJ) {
                    v0 = fmaxf(v0, 0.f); v1 = fmaxf(v1, 0.f);
                    if (z == 0) { v0 *= vv[c]; v1 *= vv[c + 1]; }
                }
                if (EPI == EPI_CTX) {
                    float2 a2 = *(const float2*)(adb + (long)r * N + c);
                    v0 = v0 * rowS[p] + a2.x;
                    v1 = v1 * rowS[p] + a2.y;
                }
                if (EPI == EPI_BIAS_RELU) { v0 = fmaxf(v0 + vv[c], 0.f); v1 = fmaxf(v1 + vv[c + 1], 0.f); }
                if (EPI == EPI_BIAS)      { v0 += vv[c]; v1 += vv[c + 1]; }
                if (OUTH) {
                    __half* op = (__half*)Cbase + cBase + (long)r * N + c;
                    *(__half2*)op = __floats2half2_rn(v0, v1);
                } else {
                    float* op = (float*)Cbase + cBase + (long)r * N + c;
                    *(float2*)op = make_float2(v0, v1);
                }
            }
        }
    }
#undef ISSUE
}

// ---------------- invs: qmask/rowsum ----------------
__global__ __launch_bounds__(256)
void invs_k(const float* __restrict__ part, const float* __restrict__ qmask,
            float* __restrict__ invs)
{
    const int i = blockIdx.x * 256 + threadIdx.x;
    float s = 0.f;
#pragma unroll
    for (int j = 0; j < 8; j++) s += part[(long)i * 8 + j];
    invs[i] = qmask[i] / s;
}

// ---------------- Q convert: f32 -> f16, plus fp32 copy to output ----------------
__global__ __launch_bounds__(256)
void convq_k(const float* __restrict__ in, __half* __restrict__ out, float* __restrict__ outc)
{
    const int i = blockIdx.x * 256 + threadIdx.x;
    float4 v = ((const float4*)in)[i];
    __half2* o = (__half2*)out + (long)i * 2;
    o[0] = __floats2half2_rn(v.x, v.y);
    o[1] = __floats2half2_rn(v.z, v.w);
    ((float4*)outc)[i] = v;
}

// ---------------- K convert + transpose: f32 [R][C] -> f16 linear + f16 [C][R] ----------------
__global__ __launch_bounds__(256)
void convkt_k(const float* __restrict__ in, __half* __restrict__ lin, __half* __restrict__ tr,
              int R, int C, long sIn, long sOut)
{
    __shared__ float t[32][33];
    const long zi = (long)blockIdx.z * sIn, zo = (long)blockIdx.z * sOut;
    const int c0 = blockIdx.x * 32, r0 = blockIdx.y * 32;
    const int tx = threadIdx.x, ty = threadIdx.y;
#pragma unroll
    for (int i = ty; i < 32; i += 8) {
        float v = in[zi + (long)(r0 + i) * C + c0 + tx];
        t[i][tx] = v;
        lin[zi + (long)(r0 + i) * C + c0 + tx] = __float2half(v);
    }
    __syncthreads();
#pragma unroll
    for (int i = ty; i < 32; i += 8)
        tr[zo + (long)(c0 + i) * R + r0 + tx] = __float2half(t[tx][i]);
}

// ---------------- f32 transpose -> f16 (square weights) ----------------
__global__ __launch_bounds__(256)
void transp_k(const float* __restrict__ in, __half* __restrict__ out, int R, int C)
{
    __shared__ float t[32][33];
    const int c0 = blockIdx.x * 32, r0 = blockIdx.y * 32;
    const int tx = threadIdx.x, ty = threadIdx.y;
#pragma unroll
    for (int i = ty; i < 32; i += 8)
        t[i][tx] = in[(long)(r0 + i) * C + c0 + tx];
    __syncthreads();
#pragma unroll
    for (int i = ty; i < 32; i += 8)
        out[(long)(c0 + i) * R + r0 + tx] = __float2half(t[tx][i]);
}

// ---------------- LayerNorm: fp32 in -> f16 out ----------------
__global__ __launch_bounds__(256)
void ln_k(const float* __restrict__ in, __half* __restrict__ out,
          const float* __restrict__ gamma, const float* __restrict__ beta)
{
    __shared__ float sh[8];
    const long row = blockIdx.x;
    const float* p = in + row * CH;
    const int tid = threadIdx.x, lane = tid & 31, w = tid >> 5;
    const int c = tid * 4;

    float4 xv = *(const float4*)(p + c);
    float s = xv.x + xv.y + xv.z + xv.w;
#pragma unroll
    for (int o = 16; o; o >>= 1) s += __shfl_xor_sync(0xffffffffu, s, o);
    if (lane == 0) sh[w] = s;
    __syncthreads();
    float tot = 0.f;
#pragma unroll
    for (int i = 0; i < 8; i++) tot += sh[i];
    const float mu = tot * (1.f / CH);

    float d0 = xv.x - mu, d1 = xv.y - mu, d2 = xv.z - mu, d3 = xv.w - mu;
    float q = d0 * d0 + d1 * d1 + d2 * d2 + d3 * d3;
#pragma unroll
    for (int o = 16; o; o >>= 1) q += __shfl_xor_sync(0xffffffffu, q, o);
    __syncthreads();
    if (lane == 0) sh[w] = q;
    __syncthreads();
    float vtot = 0.f;
#pragma unroll
    for (int i = 0; i < 8; i++) vtot += sh[i];
    const float rstd = rsqrtf(vtot * (1.f / CH) + 1e-6f);

    float4 g  = *(const float4*)(gamma + c);
    float4 be = *(const float4*)(beta + c);
    __half2* o2 = (__half2*)(out + row * CH + c);
    o2[0] = __floats2half2_rn(d0 * rstd * g.x + be.x, d1 * rstd * g.y + be.y);
    o2[1] = __floats2half2_rn(d2 * rstd * g.z + be.z, d3 * rstd * g.w + be.w);
}

// ---------------- launch ----------------
extern "C" void kernel_launch(void* const* d_in, const int* in_sizes, int n_in,
                              void* d_out, int out_size)
{
    const float* Q     = (const float*)d_in[0];
    const float* Kk    = (const float*)d_in[1];
    const float* kmask = (const float*)d_in[2];
    const float* qmask = (const float*)d_in[3];
    const float* u     = (const float*)d_in[4];
    const float* dd    = (const float*)d_in[5];
    const float* W1    = (const float*)d_in[6];
    const float* b1    = (const float*)d_in[7];
    const float* W2    = (const float*)d_in[8];
    const float* b2    = (const float*)d_in[9];
    const float* gamma = (const float*)d_in[10];
    const float* beta  = (const float*)d_in[11];

    __half *hQ, *hK, *hKT, *hUT, *hW1T, *hW2T, *f1h, *f2h, *hS, *hLN, *hH;
    float  *ctx, *part, *invs;
    cudaGetSymbolAddress((void**)&hQ,  g_hQ);
    cudaGetSymbolAddress((void**)&hK,  g_hK);
    cudaGetSymbolAddress((void**)&hKT, g_hKT);
    cudaGetSymbolAddress((void**)&hUT, g_hUT);
    cudaGetSymbolAddress((void**)&hW1T, g_hW1T);
    cudaGetSymbolAddress((void**)&hW2T, g_hW2T);
    cudaGetSymbolAddress((void**)&f1h, g_f1h);
    cudaGetSymbolAddress((void**)&f2h, g_f2h);
    cudaGetSymbolAddress((void**)&hS,  g_hS);
    cudaGetSymbolAddress((void**)&ctx, g_ctx);
    cudaGetSymbolAddress((void**)&hLN, g_hLN);
    cudaGetSymbolAddress((void**)&hH,  g_hH);
    cudaGetSymbolAddress((void**)&part, g_part);
    cudaGetSymbolAddress((void**)&invs, g_invs);

    const long TC  = (long)TT * CH;
    const long TTl = (long)TT * TT;

    float* out2 = (float*)d_out;
    float* outq = (float*)d_out;
    if ((long)out_size >= 2 * (long)NTC) out2 = (float*)d_out + NTC;

    cudaFuncSetAttribute(gemmv5<EPI_PROJ, true>,      cudaFuncAttributeMaxDynamicSharedMemorySize, SMEM_G);
    cudaFuncSetAttribute(gemmv5<EPI_EXP, true>,       cudaFuncAttributeMaxDynamicSharedMemorySize, SMEM_G);
    cudaFuncSetAttribute(gemmv5<EPI_CTX, false>,      cudaFuncAttributeMaxDynamicSharedMemorySize, SMEM_G);
    cudaFuncSetAttribute(gemmv5<EPI_BIAS_RELU, true>, cudaFuncAttributeMaxDynamicSharedMemorySize, SMEM_G);
    cudaFuncSetAttribute(gemmv5<EPI_BIAS, false>,     cudaFuncAttributeMaxDynamicSharedMemorySize, SMEM_G);

    // ---- conversions (6th launch = merged projection GEMM, for ncu -s 5) ----
    convq_k<<<NTC / 1024, 256>>>(Q, hQ, outq);                                   // 1
    transp_k<<<dim3(CH / 32, CH / 32), dim3(32, 8)>>>(u,  hUT,  CH, CH);         // 2
    transp_k<<<dim3(CH / 32, CH / 32), dim3(32, 8)>>>(W1, hW1T, CH, CH);         // 3
    transp_k<<<dim3(CH / 32, CH / 32), dim3(32, 8)>>>(W2, hW2T, CH, CH);         // 4
    convkt_k<<<dim3(CH / 32, TT / 32, BB), dim3(32, 8)>>>(Kk, hK, hKT, TT, CH, TC, TC); // 5

    // ---- 1+2) f1 = relu(Q@u)*d ; f2 = relu(K@u)  (merged, grid.z=2) ----        6 (profiled)
    gemmv5<EPI_PROJ, true><<<dim3(CH / BN, BB * TT / BM, 2), NTHR, SMEM_G>>>(
        hQ, hK, hUT, f1h, f2h, BB * TT, CH, CH, 0, 0, 0, dd, 0, nullptr, 0, 0.f, nullptr);

    // ---- 3) expS = exp((f1 @ f2^T)/32) masked, + row partial sums ----
    gemmv5<EPI_EXP, true><<<dim3(TT / BN, TT / BM, BB), NTHR, SMEM_G>>>(
        f1h, nullptr, f2h, hS, nullptr, TT, TT, CH, TC, TC, TTl, kmask, TT, nullptr, 0,
        1.0f / 32.0f, part);

    // ---- 4) invs = qmask / rowsum ----
    invs_k<<<BB * TT / 256, 256>>>(part, qmask, invs);

    // ---- 5) ctx = (expS @ K) * invs[row] + Q  (fp32) ----
    gemmv5<EPI_CTX, false><<<dim3(CH / BN, TT / BM, BB), NTHR, SMEM_G>>>(
        hS, nullptr, hKT, ctx, nullptr, TT, CH, TT, TTl, TC, TC, invs, TT, Q, TC, 0.f, nullptr);

    // ---- 6) LayerNorm -> f16 ----
    ln_k<<<BB * TT, 256>>>(ctx, hLN, gamma, beta);

    // ---- 7) h = relu(LN @ W1 + b1) -> f16 ----
    gemmv5<EPI_BIAS_RELU, true><<<dim3(CH / BN, BB * TT / BM, 1), NTHR, SMEM_G>>>(
        hLN, nullptr, hW1T, hH, nullptr, BB * TT, CH, CH, 0, 0, 0, b1, 0, nullptr, 0, 0.f, nullptr);

    // ---- 8) out2 = h @ W2 + b2 (fp32) ----
    gemmv5<EPI_BIAS, false><<<dim3(CH / BN, BB * TT / BM, 1), NTHR, SMEM_G>>>(
        hH, nullptr, hW2T, out2, nullptr, BB * TT, CH, CH, 0, 0, 0, b2, 0, nullptr, 0, 0.f, nullptr);
}